// round 1
// baseline (speedup 1.0000x reference)
#include <cuda_runtime.h>
#include <math.h>

// ---------------- problem dims ----------------
#define NB   2048    // E*S
#define IN_  2048
#define H_   1024
#define L_   32
#define OUT_ 64
#define QH   256     // H/4 (per-branch out channels)

// ---------------- scratch (device globals; no allocation allowed) ----------------
__device__ float g_xr[(size_t)NB * H_];                 // 8 MB
__device__ float g_hs[(size_t)L_ * NB * H_];            // 256 MB  [l][n][h]
__device__ float g_y [(size_t)L_ * NB * H_];            // 256 MB  [l][n][c] pre-BN conv out
__device__ float g_wc[(size_t)16 * H_ * QH];            // 16 MB   16 slabs [i][o_local]
__device__ float g_bias[H_];
__device__ float g_psum [64 * H_];
__device__ float g_psumsq[64 * H_];
__device__ float g_scale[H_];
__device__ float g_shift[H_];

// ---------------- weight prep: OIH -> per-(branch,tap) [H][256] K-major slabs ----------------
__global__ void prep_kernel(const float* __restrict__ w1, const float* __restrict__ b1,
                            const float* __restrict__ w3, const float* __restrict__ b3,
                            const float* __restrict__ w5, const float* __restrict__ b5,
                            const float* __restrict__ w7, const float* __restrict__ b7)
{
    int idx = blockIdx.x * 256 + threadIdx.x;
    const int total = 16 * H_ * QH;
    if (idx < total) {
        int s   = idx / (H_ * QH);
        int rem = idx - s * (H_ * QH);
        int i   = rem >> 8;       // input channel
        int o   = rem & 255;      // branch-local out channel
        int b, t;
        if (s == 0)      { b = 0; t = 0;     }
        else if (s < 4)  { b = 1; t = s - 1; }
        else if (s < 9)  { b = 2; t = s - 4; }
        else             { b = 3; t = s - 9; }
        const float* w = (b == 0) ? w1 : (b == 1) ? w3 : (b == 2) ? w5 : w7;
        int kb = 2 * b + 1;
        g_wc[idx] = w[((size_t)o * H_ + i) * kb + t];
    }
    if (idx < H_) {
        int b = idx >> 8, o = idx & 255;
        const float* bb = (b == 0) ? b1 : (b == 1) ? b3 : (b == 2) ? b5 : b7;
        g_bias[idx] = bb[o];
    }
}

// ---------------- GEMM 1: x_r = hwa @ Wx + bx   (M=2048,N=1024,K=2048; BM=128,BN=64,BK=8) ----------------
__global__ void __launch_bounds__(256) xr_kernel(const float* __restrict__ A,
                                                 const float* __restrict__ Bm,
                                                 const float* __restrict__ bx)
{
    __shared__ __align__(16) float As[8][128];
    __shared__ __align__(16) float Bs[8][64];
    const int m0 = blockIdx.y * 128, n0 = blockIdx.x * 64;
    const int tid  = threadIdx.x;
    const int arow = tid >> 1, acol = (tid & 1) * 4;
    const int brow = tid >> 5, bcol = (tid & 31) * 2;
    const int ty   = tid >> 4, tx   = tid & 15;
    float acc[8][4] = {};

    for (int k0 = 0; k0 < IN_; k0 += 8) {
        float4 av = *(const float4*)(A + (size_t)(m0 + arow) * IN_ + k0 + acol);
        float2 bv = *(const float2*)(Bm + (size_t)(k0 + brow) * H_ + n0 + bcol);
        As[acol + 0][arow] = av.x; As[acol + 1][arow] = av.y;
        As[acol + 2][arow] = av.z; As[acol + 3][arow] = av.w;
        *(float2*)&Bs[brow][bcol] = bv;
        __syncthreads();
#pragma unroll
        for (int kk = 0; kk < 8; kk++) {
            float a[8], b[4];
            ((float4*)a)[0] = *(const float4*)&As[kk][ty * 8];
            ((float4*)a)[1] = *(const float4*)&As[kk][ty * 8 + 4];
            ((float4*)b)[0] = *(const float4*)&Bs[kk][tx * 4];
#pragma unroll
            for (int i = 0; i < 8; i++)
#pragma unroll
                for (int j = 0; j < 4; j++) acc[i][j] += a[i] * b[j];
        }
        __syncthreads();
    }
    const int c0 = n0 + tx * 4;
    float4 bb = *(const float4*)(bx + c0);
#pragma unroll
    for (int i = 0; i < 8; i++) {
        int r = m0 + ty * 8 + i;
        float4 v;
        v.x = acc[i][0] + bb.x; v.y = acc[i][1] + bb.y;
        v.z = acc[i][2] + bb.z; v.w = acc[i][3] + bb.w;
        *(float4*)&g_xr[(size_t)r * H_ + c0] = v;
    }
}

// ---------------- RNN step 0 (h0 = 0): hs[0] = 0.5 * tanh(x_r + bh) ----------------
__global__ void step0_kernel(const float* __restrict__ bh)
{
    int i = blockIdx.x * 256 + threadIdx.x;           // NB*H threads
    int c = i & (H_ - 1);
    g_hs[i] = 0.5f * tanhf(g_xr[i] + bh[c]);
}

// ---------------- RNN step l>=1: hs[l] = 0.5*hs[l-1] + 0.5*tanh(x_r + hs[l-1]@Wh + bh) ----------------
__global__ void __launch_bounds__(256) rnn_kernel(const float* __restrict__ Wh,
                                                  const float* __restrict__ bh, int l)
{
    __shared__ __align__(16) float As[8][128];
    __shared__ __align__(16) float Bs[8][64];
    const float* A   = g_hs + (size_t)(l - 1) * NB * H_;
    float*       Dst = g_hs + (size_t)l       * NB * H_;
    const int m0 = blockIdx.y * 128, n0 = blockIdx.x * 64;
    const int tid  = threadIdx.x;
    const int arow = tid >> 1, acol = (tid & 1) * 4;
    const int brow = tid >> 5, bcol = (tid & 31) * 2;
    const int ty   = tid >> 4, tx   = tid & 15;
    float acc[8][4] = {};

    for (int k0 = 0; k0 < H_; k0 += 8) {
        float4 av = *(const float4*)(A + (size_t)(m0 + arow) * H_ + k0 + acol);
        float2 bv = *(const float2*)(Wh + (size_t)(k0 + brow) * H_ + n0 + bcol);
        As[acol + 0][arow] = av.x; As[acol + 1][arow] = av.y;
        As[acol + 2][arow] = av.z; As[acol + 3][arow] = av.w;
        *(float2*)&Bs[brow][bcol] = bv;
        __syncthreads();
#pragma unroll
        for (int kk = 0; kk < 8; kk++) {
            float a[8], b[4];
            ((float4*)a)[0] = *(const float4*)&As[kk][ty * 8];
            ((float4*)a)[1] = *(const float4*)&As[kk][ty * 8 + 4];
            ((float4*)b)[0] = *(const float4*)&Bs[kk][tx * 4];
#pragma unroll
            for (int i = 0; i < 8; i++)
#pragma unroll
                for (int j = 0; j < 4; j++) acc[i][j] += a[i] * b[j];
        }
        __syncthreads();
    }
    const int c0 = n0 + tx * 4;
    float4 bb = *(const float4*)(bh + c0);
#pragma unroll
    for (int i = 0; i < 8; i++) {
        size_t base = (size_t)(m0 + ty * 8 + i) * H_ + c0;
        float4 hp = *(const float4*)(A    + base);
        float4 xr = *(const float4*)(g_xr + base);
        float4 v;
        v.x = 0.5f * hp.x + 0.5f * tanhf(xr.x + acc[i][0] + bb.x);
        v.y = 0.5f * hp.y + 0.5f * tanhf(xr.y + acc[i][1] + bb.y);
        v.z = 0.5f * hp.z + 0.5f * tanhf(xr.z + acc[i][2] + bb.z);
        v.w = 0.5f * hp.w + 0.5f * tanhf(xr.w + acc[i][3] + bb.w);
        *(float4*)(Dst + base) = v;
    }
}

// ---------------- conv: tap-decomposed GEMM, tile 128(n) x 128(o), per-tile branch ----------------
__global__ void __launch_bounds__(256) conv_kernel()
{
    __shared__ __align__(16) float As[8][128];
    __shared__ __align__(16) float Bs[8][128];
    const int n0 = blockIdx.x * 128;
    const int o0 = blockIdx.y * 128;
    const int l  = blockIdx.z;
    const int b  = o0 >> 8;                 // branch 0..3, kernel = 2b+1, pad = b
    const int kb = 2 * b + 1;
    const int sbase  = (b == 0) ? 0 : (b == 1) ? 1 : (b == 2) ? 4 : 9;
    const int olocal = o0 & 255;

    const int tid  = threadIdx.x;
    const int arow = tid >> 1, acol = (tid & 1) * 4;
    const int brow = tid >> 5, bcol = (tid & 31) * 4;
    const int ty   = tid >> 4, tx   = tid & 15;
    float acc[8][8] = {};

    for (int t = 0; t < kb; t++) {
        int lsrc = l + t - b;
        if (lsrc < 0 || lsrc >= L_) continue;           // zero padding: uniform per block
        const float* A  = g_hs + ((size_t)lsrc * NB + n0) * H_;
        const float* Bp = g_wc + (size_t)(sbase + t) * H_ * QH + olocal;
        for (int k0 = 0; k0 < H_; k0 += 8) {
            float4 av = *(const float4*)(A  + (size_t)arow * H_ + k0 + acol);
            float4 bv = *(const float4*)(Bp + (size_t)(k0 + brow) * QH + bcol);
            As[acol + 0][arow] = av.x; As[acol + 1][arow] = av.y;
            As[acol + 2][arow] = av.z; As[acol + 3][arow] = av.w;
            *(float4*)&Bs[brow][bcol] = bv;
            __syncthreads();
#pragma unroll
            for (int kk = 0; kk < 8; kk++) {
                float a[8], bb[8];
                ((float4*)a)[0]  = *(const float4*)&As[kk][ty * 8];
                ((float4*)a)[1]  = *(const float4*)&As[kk][ty * 8 + 4];
                ((float4*)bb)[0] = *(const float4*)&Bs[kk][tx * 8];
                ((float4*)bb)[1] = *(const float4*)&Bs[kk][tx * 8 + 4];
#pragma unroll
                for (int i = 0; i < 8; i++)
#pragma unroll
                    for (int j = 0; j < 8; j++) acc[i][j] += a[i] * bb[j];
            }
            __syncthreads();
        }
    }
    const int c0 = o0 + tx * 8;
    float4 bia0 = *(const float4*)(g_bias + c0);
    float4 bia1 = *(const float4*)(g_bias + c0 + 4);
#pragma unroll
    for (int i = 0; i < 8; i++) {
        size_t base = ((size_t)l * NB + n0 + ty * 8 + i) * H_ + c0;
        float4 v0, v1;
        v0.x = acc[i][0] + bia0.x; v0.y = acc[i][1] + bia0.y;
        v0.z = acc[i][2] + bia0.z; v0.w = acc[i][3] + bia0.w;
        v1.x = acc[i][4] + bia1.x; v1.y = acc[i][5] + bia1.y;
        v1.z = acc[i][6] + bia1.z; v1.w = acc[i][7] + bia1.w;
        *(float4*)&g_y[base]     = v0;
        *(float4*)&g_y[base + 4] = v1;
    }
}

// ---------------- BN stats: deterministic two-stage reduction ----------------
__global__ void stats_partial()
{
    __shared__ float ss[8][32], sq[8][32];
    int tx = threadIdx.x, ty = threadIdx.y;
    int c  = blockIdx.x * 32 + tx;
    int r0 = blockIdx.y * 1024;                 // 64 row-partitions of 1024 rows
    float s = 0.f, q = 0.f;
    for (int r = r0 + ty; r < r0 + 1024; r += 8) {
        float v = g_y[(size_t)r * H_ + c];
        s += v; q += v * v;
    }
    ss[ty][tx] = s; sq[ty][tx] = q;
    __syncthreads();
    if (ty == 0) {
        float S = 0.f, Q = 0.f;
#pragma unroll
        for (int j = 0; j < 8; j++) { S += ss[j][tx]; Q += sq[j][tx]; }
        g_psum  [blockIdx.y * H_ + c] = S;
        g_psumsq[blockIdx.y * H_ + c] = Q;
    }
}

__global__ void finalize_kernel(const float* __restrict__ gamma, const float* __restrict__ beta)
{
    int c = blockIdx.x * 256 + threadIdx.x;
    if (c >= H_) return;
    float s = 0.f, q = 0.f;
    for (int p = 0; p < 64; p++) { s += g_psum[p * H_ + c]; q += g_psumsq[p * H_ + c]; }
    const float invM = 1.0f / (float)(NB * L_);
    float mean = s * invM;
    float var  = q * invM - mean * mean;
    float rstd = rsqrtf(var + 1e-5f);
    float sc   = rstd * gamma[c];
    g_scale[c] = sc;
    g_shift[c] = beta[c] - mean * sc;
}

// ---------------- final: out = PReLU(BN(y)) @ Wout + bout   (BN+PReLU folded into A-load) ----------------
__global__ void __launch_bounds__(256) out_kernel(const float* __restrict__ Wout,
                                                  const float* __restrict__ bout,
                                                  const float* __restrict__ prelu,
                                                  float* __restrict__ out)
{
    __shared__ __align__(16) float As[8][128];
    __shared__ __align__(16) float Bs[8][64];
    const int l  = blockIdx.y;
    const int n0 = blockIdx.x * 128;
    const float pa = *prelu;
    const float* A = g_y + ((size_t)l * NB + n0) * H_;
    const int tid  = threadIdx.x;
    const int arow = tid >> 1, acol = (tid & 1) * 4;
    const int brow = tid >> 5, bcol = (tid & 31) * 2;
    const int ty   = tid >> 4, tx   = tid & 15;
    float acc[8][4] = {};

    for (int k0 = 0; k0 < H_; k0 += 8) {
        float4 av = *(const float4*)(A + (size_t)arow * H_ + k0 + acol);
        float4 sc = *(const float4*)(g_scale + k0 + acol);
        float4 sh = *(const float4*)(g_shift + k0 + acol);
        float v0 = av.x * sc.x + sh.x; v0 = (v0 > 0.f) ? v0 : pa * v0;
        float v1 = av.y * sc.y + sh.y; v1 = (v1 > 0.f) ? v1 : pa * v1;
        float v2 = av.z * sc.z + sh.z; v2 = (v2 > 0.f) ? v2 : pa * v2;
        float v3 = av.w * sc.w + sh.w; v3 = (v3 > 0.f) ? v3 : pa * v3;
        As[acol + 0][arow] = v0; As[acol + 1][arow] = v1;
        As[acol + 2][arow] = v2; As[acol + 3][arow] = v3;
        float2 bv = *(const float2*)(Wout + (size_t)(k0 + brow) * OUT_ + bcol);
        *(float2*)&Bs[brow][bcol] = bv;
        __syncthreads();
#pragma unroll
        for (int kk = 0; kk < 8; kk++) {
            float a[8], b[4];
            ((float4*)a)[0] = *(const float4*)&As[kk][ty * 8];
            ((float4*)a)[1] = *(const float4*)&As[kk][ty * 8 + 4];
            ((float4*)b)[0] = *(const float4*)&Bs[kk][tx * 4];
#pragma unroll
            for (int i = 0; i < 8; i++)
#pragma unroll
                for (int j = 0; j < 4; j++) acc[i][j] += a[i] * b[j];
        }
        __syncthreads();
    }
    const int o0 = tx * 4;
    float4 bb = *(const float4*)(bout + o0);
#pragma unroll
    for (int i = 0; i < 8; i++) {
        int n = n0 + ty * 8 + i;
        float4 v;
        v.x = acc[i][0] + bb.x; v.y = acc[i][1] + bb.y;
        v.z = acc[i][2] + bb.z; v.w = acc[i][3] + bb.w;
        *(float4*)&out[((size_t)n * L_ + l) * OUT_ + o0] = v;
    }
}

// ---------------- launch ----------------
extern "C" void kernel_launch(void* const* d_in, const int* in_sizes, int n_in,
                              void* d_out, int out_size)
{
    const float* hwa   = (const float*)d_in[0];
    const float* Wx    = (const float*)d_in[1];
    const float* bx    = (const float*)d_in[2];
    const float* Wh    = (const float*)d_in[3];
    const float* bh    = (const float*)d_in[4];
    const float* w1    = (const float*)d_in[5];
    const float* b1    = (const float*)d_in[6];
    const float* w3    = (const float*)d_in[7];
    const float* b3    = (const float*)d_in[8];
    const float* w5    = (const float*)d_in[9];
    const float* b5    = (const float*)d_in[10];
    const float* w7    = (const float*)d_in[11];
    const float* b7    = (const float*)d_in[12];
    const float* gamma = (const float*)d_in[13];
    const float* beta  = (const float*)d_in[14];
    const float* prelu = (const float*)d_in[15];
    const float* Wout  = (const float*)d_in[16];
    const float* bout  = (const float*)d_in[17];
    float* out = (float*)d_out;

    prep_kernel<<<(16 * H_ * QH + 255) / 256, 256>>>(w1, b1, w3, b3, w5, b5, w7, b7);
    xr_kernel<<<dim3(H_ / 64, NB / 128), 256>>>(hwa, Wx, bx);
    step0_kernel<<<(NB * H_) / 256, 256>>>(bh);
    for (int l = 1; l < L_; l++)
        rnn_kernel<<<dim3(H_ / 64, NB / 128), 256>>>(Wh, bh, l);
    conv_kernel<<<dim3(NB / 128, H_ / 128, L_), 256>>>();
    stats_partial<<<dim3(H_ / 32, 64), dim3(32, 8)>>>();
    finalize_kernel<<<(H_ + 255) / 256, 256>>>(gamma, beta);
    out_kernel<<<dim3(NB / 128, L_), 256>>>(Wout, bout, prelu, out);
}

// round 7
// speedup vs baseline: 2.9351x; 2.9351x over previous
#include <cuda_runtime.h>
#include <cuda_bf16.h>
#include <math.h>
#include <stdint.h>

// ---------------- problem dims ----------------
#define NB   2048    // E*S
#define IN_  2048
#define H_   1024
#define L_   32
#define OUT_ 64
#define QH   256     // H/4 per-branch out channels

// ---------------- scratch (device globals; no allocation allowed) ----------------
__device__ __align__(128) float          g_xr  [(size_t)NB * H_];          // 8 MB
__device__ __align__(128) __nv_bfloat16  g_hshi[(size_t)L_ * NB * H_];     // 128 MB [l][n][h]
__device__ __align__(128) __nv_bfloat16  g_hslo[(size_t)L_ * NB * H_];     // 128 MB
__device__ __align__(128) float          g_y   [(size_t)L_ * NB * H_];     // 256 MB [l][n][c]
__device__ __align__(128) __nv_bfloat16  g_whhi[(size_t)H_ * H_];          // WhT [n][k]
__device__ __align__(128) __nv_bfloat16  g_whlo[(size_t)H_ * H_];
__device__ __align__(128) __nv_bfloat16  g_wchi[(size_t)16 * QH * H_];     // [slab][o][k]
__device__ __align__(128) __nv_bfloat16  g_wclo[(size_t)16 * QH * H_];
__device__ float g_bias[H_];
__device__ float g_psum [64 * H_];
__device__ float g_psumsq[64 * H_];
__device__ float g_scale[H_];
__device__ float g_shift[H_];

// ---------------- helpers ----------------
__device__ __forceinline__ uint32_t smem_u32(const void* p) {
    uint32_t a;
    asm("{ .reg .u64 t; cvta.to.shared.u64 t, %1; cvt.u32.u64 %0, t; }" : "=r"(a) : "l"(p));
    return a;
}

#define CP16(dst, src) \
    asm volatile("cp.async.cg.shared.global [%0], [%1], 16;" :: "r"(dst), "l"(src))
#define CP_COMMIT() asm volatile("cp.async.commit_group;")
#define CP_WAIT1()  asm volatile("cp.async.wait_group 1;")
#define CP_WAIT0()  asm volatile("cp.async.wait_group 0;")

#define LDSM4(r0, r1, r2, r3, addr)                                          \
    asm volatile("ldmatrix.sync.aligned.m8n8.x4.shared.b16 {%0,%1,%2,%3}, [%4];" \
        : "=r"(r0), "=r"(r1), "=r"(r2), "=r"(r3) : "r"(addr))

#define MMA_BF16(d, a, b)                                                     \
    asm volatile("mma.sync.aligned.m16n8k16.row.col.f32.bf16.bf16.f32 "       \
        "{%0,%1,%2,%3}, {%4,%5,%6,%7}, {%8,%9}, {%0,%1,%2,%3};"               \
        : "+f"((d)[0]), "+f"((d)[1]), "+f"((d)[2]), "+f"((d)[3])              \
        : "r"((a)[0]), "r"((a)[1]), "r"((a)[2]), "r"((a)[3]),                 \
          "r"((b)[0]), "r"((b)[1]))

__device__ __forceinline__ void split_bf16(float x, __nv_bfloat16& hi, __nv_bfloat16& lo) {
    hi = __float2bfloat16(x);
    lo = __float2bfloat16(x - __bfloat162float(hi));
}

// issue one 128x64 bf16 tile (row stride H_) into XOR-swizzled smem via cp.async
__device__ __forceinline__ void issue_tile(uint32_t dst, const __nv_bfloat16* __restrict__ src, int tid) {
#pragma unroll
    for (int i = 0; i < 4; i++) {
        int u = tid + 256 * i;
        int r = u >> 3, cu = u & 7;
        uint32_t sw = (uint32_t)(r * 128) + (uint32_t)(((cu ^ (r & 7)) << 4));
        CP16(dst + sw, (const void*)(src + (size_t)r * H_ + cu * 8));
    }
}

// one K=64 chunk of the 3-term bf16 MMA: acc += Ahi*Bhi + Ahi*Blo + Alo*Bhi
// buf layout: [Ahi 16K][Alo 16K][Bhi 16K][Blo 16K]; wm = warp m-offset, wn = warp n-offset
__device__ __forceinline__ void mma_chunk(uint32_t buf, int wm, int wn, int lane,
                                          float acc[2][8][4]) {
    const uint32_t Ahi = buf, Alo = buf + 16384, Bhi = buf + 32768, Blo = buf + 49152;
#pragma unroll
    for (int ks = 0; ks < 4; ks++) {
        uint32_t a[2][2][4];
        const int arow0 = wm + (lane & 7) + ((lane >> 3) & 1) * 8;
        const int acu   = 2 * ks + (lane >> 4);
#pragma unroll
        for (int mt = 0; mt < 2; mt++) {
            int r = arow0 + mt * 16;
            uint32_t off = (uint32_t)(r * 128 + ((acu ^ (r & 7)) << 4));
            LDSM4(a[0][mt][0], a[0][mt][1], a[0][mt][2], a[0][mt][3], Ahi + off);
            LDSM4(a[1][mt][0], a[1][mt][1], a[1][mt][2], a[1][mt][3], Alo + off);
        }
        uint32_t b[2][8][2];
        const int brow0 = wn + (lane & 7) + ((lane >> 4) & 1) * 8;
        const int bcu   = 2 * ks + ((lane >> 3) & 1);
#pragma unroll
        for (int p = 0; p < 4; p++) {
            int r = brow0 + p * 16;
            uint32_t off = (uint32_t)(r * 128 + ((bcu ^ (r & 7)) << 4));
            uint32_t r0, r1, r2, r3;
            LDSM4(r0, r1, r2, r3, Bhi + off);
            b[0][2*p][0] = r0; b[0][2*p][1] = r1; b[0][2*p+1][0] = r2; b[0][2*p+1][1] = r3;
            LDSM4(r0, r1, r2, r3, Blo + off);
            b[1][2*p][0] = r0; b[1][2*p][1] = r1; b[1][2*p+1][0] = r2; b[1][2*p+1][1] = r3;
        }
#pragma unroll
        for (int mt = 0; mt < 2; mt++)
#pragma unroll
            for (int nt = 0; nt < 8; nt++) {
                MMA_BF16(acc[mt][nt], a[0][mt], b[0][nt]);
                MMA_BF16(acc[mt][nt], a[0][mt], b[1][nt]);
                MMA_BF16(acc[mt][nt], a[1][mt], b[0][nt]);
            }
    }
}

// ---------------- weight prep ----------------
__global__ void prep_wh(const float* __restrict__ Wh) {
    int idx = blockIdx.x * 256 + threadIdx.x;      // over H*H, [n][k]
    int n = idx >> 10, k = idx & 1023;
    float w = Wh[(size_t)k * H_ + n];
    __nv_bfloat16 hi, lo; split_bf16(w, hi, lo);
    g_whhi[idx] = hi; g_whlo[idx] = lo;
}

__global__ void prep_wc(const float* __restrict__ w1, const float* __restrict__ b1,
                        const float* __restrict__ w3, const float* __restrict__ b3,
                        const float* __restrict__ w5, const float* __restrict__ b5,
                        const float* __restrict__ w7, const float* __restrict__ b7) {
    int idx = blockIdx.x * 256 + threadIdx.x;      // over 16*QH*H_, [s][o][k]
    int s   = idx / (QH * H_);
    int rem = idx - s * (QH * H_);
    int o   = rem >> 10;
    int k   = rem & 1023;
    int b, t;
    if (s == 0)      { b = 0; t = 0;     }
    else if (s < 4)  { b = 1; t = s - 1; }
    else if (s < 9)  { b = 2; t = s - 4; }
    else             { b = 3; t = s - 9; }
    const float* w = (b == 0) ? w1 : (b == 1) ? w3 : (b == 2) ? w5 : w7;
    int kb = 2 * b + 1;
    float val = w[((size_t)o * H_ + k) * kb + t];
    __nv_bfloat16 hi, lo; split_bf16(val, hi, lo);
    g_wchi[idx] = hi; g_wclo[idx] = lo;
    if (idx < H_) {
        int bb = idx >> 8, oo = idx & 255;
        const float* bp = (bb == 0) ? b1 : (bb == 1) ? b3 : (bb == 2) ? b5 : b7;
        g_bias[idx] = bp[oo];
    }
}

// ---------------- GEMM 1 (SIMT fp32): x_r = hwa @ Wx + bx ----------------
__global__ void __launch_bounds__(256) xr_kernel(const float* __restrict__ A,
                                                 const float* __restrict__ Bm,
                                                 const float* __restrict__ bx) {
    __shared__ __align__(16) float As[8][128];
    __shared__ __align__(16) float Bs[8][64];
    const int m0 = blockIdx.y * 128, n0 = blockIdx.x * 64;
    const int tid  = threadIdx.x;
    const int arow = tid >> 1, acol = (tid & 1) * 4;
    const int brow = tid >> 5, bcol = (tid & 31) * 2;
    const int ty   = tid >> 4, tx   = tid & 15;
    float acc[8][4] = {};
    for (int k0 = 0; k0 < IN_; k0 += 8) {
        float4 av = *(const float4*)(A + (size_t)(m0 + arow) * IN_ + k0 + acol);
        float2 bv = *(const float2*)(Bm + (size_t)(k0 + brow) * H_ + n0 + bcol);
        As[acol + 0][arow] = av.x; As[acol + 1][arow] = av.y;
        As[acol + 2][arow] = av.z; As[acol + 3][arow] = av.w;
        *(float2*)&Bs[brow][bcol] = bv;
        __syncthreads();
#pragma unroll
        for (int kk = 0; kk < 8; kk++) {
            float a[8], b[4];
            ((float4*)a)[0] = *(const float4*)&As[kk][ty * 8];
            ((float4*)a)[1] = *(const float4*)&As[kk][ty * 8 + 4];
            ((float4*)b)[0] = *(const float4*)&Bs[kk][tx * 4];
#pragma unroll
            for (int i = 0; i < 8; i++)
#pragma unroll
                for (int j = 0; j < 4; j++) acc[i][j] += a[i] * b[j];
        }
        __syncthreads();
    }
    const int c0 = n0 + tx * 4;
    float4 bb = *(const float4*)(bx + c0);
#pragma unroll
    for (int i = 0; i < 8; i++) {
        int r = m0 + ty * 8 + i;
        float4 v;
        v.x = acc[i][0] + bb.x; v.y = acc[i][1] + bb.y;
        v.z = acc[i][2] + bb.z; v.w = acc[i][3] + bb.w;
        *(float4*)&g_xr[(size_t)r * H_ + c0] = v;
    }
}

// ---------------- step 0: hs[0] = 0.5*tanh(x_r + bh), split bf16 ----------------
__global__ void step0_kernel(const float* __restrict__ bh) {
    int i = blockIdx.x * 256 + threadIdx.x;
    int c = i & (H_ - 1);
    float v = 0.5f * tanhf(g_xr[i] + bh[c]);
    __nv_bfloat16 hi, lo; split_bf16(v, hi, lo);
    g_hshi[i] = hi; g_hslo[i] = lo;
}

// ---------------- RNN step (HMMA): hs[l] = 0.5*hs[l-1] + 0.5*tanh(xr + hs[l-1]@Wh + bh) ----------------
// grid (8 n-tiles, 16 m-tiles), 256 thr, dyn smem = 2*65536
__global__ void __launch_bounds__(256) rnn_mma(const float* __restrict__ bh, int l) {
    extern __shared__ char smem[];
    uint32_t sb = smem_u32(smem);
    const int tid = threadIdx.x, wid = tid >> 5, lane = tid & 31;
    const int n0 = blockIdx.x * 128, m0 = blockIdx.y * 128;
    const int wm = (wid & 3) * 32, wn = (wid >> 2) * 64;

    const __nv_bfloat16* Ahi = g_hshi + ((size_t)(l - 1) * NB + m0) * H_;
    const __nv_bfloat16* Alo = g_hslo + ((size_t)(l - 1) * NB + m0) * H_;
    const __nv_bfloat16* Bhi = g_whhi + (size_t)n0 * H_;
    const __nv_bfloat16* Blo = g_whlo + (size_t)n0 * H_;

    float acc[2][8][4] = {};

    // prologue: chunk 0 -> buf0
    issue_tile(sb,         Ahi, tid);
    issue_tile(sb + 16384, Alo, tid);
    issue_tile(sb + 32768, Bhi, tid);
    issue_tile(sb + 49152, Blo, tid);
    CP_COMMIT();

    for (int c = 0; c < 16; c++) {
        if (c < 15) {
            uint32_t nb = sb + ((c + 1) & 1) * 65536;
            int off = (c + 1) * 64;
            issue_tile(nb,         Ahi + off, tid);
            issue_tile(nb + 16384, Alo + off, tid);
            issue_tile(nb + 32768, Bhi + off, tid);
            issue_tile(nb + 49152, Blo + off, tid);
            CP_COMMIT();
            CP_WAIT1();
        } else {
            CP_WAIT0();
        }
        __syncthreads();
        mma_chunk(sb + (c & 1) * 65536, wm, wn, lane, acc);
        __syncthreads();
    }

    // epilogue: fused leaky-tanh + re-split
    const int g = lane >> 2, t4 = (lane & 3) * 2;
    const size_t prevB = (size_t)(l - 1) * NB * H_;
    const size_t curB  = (size_t)l * NB * H_;
#pragma unroll
    for (int mt = 0; mt < 2; mt++)
#pragma unroll
        for (int nt = 0; nt < 8; nt++)
#pragma unroll
            for (int hf = 0; hf < 2; hf++) {
                int r = m0 + wm + mt * 16 + g + hf * 8;
                int c = n0 + wn + nt * 8 + t4;
                size_t base = (size_t)r * H_ + c;
                float ax = acc[mt][nt][hf * 2 + 0];
                float ay = acc[mt][nt][hf * 2 + 1];
                float2 xr2 = *(const float2*)&g_xr[base];
                float2 bh2 = *(const float2*)&bh[c];
                __nv_bfloat162 ph = *(const __nv_bfloat162*)&g_hshi[prevB + base];
                __nv_bfloat162 pl = *(const __nv_bfloat162*)&g_hslo[prevB + base];
                float hp0 = __bfloat162float(ph.x) + __bfloat162float(pl.x);
                float hp1 = __bfloat162float(ph.y) + __bfloat162float(pl.y);
                float h0 = 0.5f * hp0 + 0.5f * tanhf(xr2.x + ax + bh2.x);
                float h1 = 0.5f * hp1 + 0.5f * tanhf(xr2.y + ay + bh2.y);
                __nv_bfloat162 vh, vl;
                __nv_bfloat16 hh, hl;
                split_bf16(h0, hh, hl); vh.x = hh; vl.x = hl;
                split_bf16(h1, hh, hl); vh.y = hh; vl.y = hl;
                *(__nv_bfloat162*)&g_hshi[curB + base] = vh;
                *(__nv_bfloat162*)&g_hslo[curB + base] = vl;
            }
}

// ---------------- conv (HMMA): tap-decomposed GEMM, CTA tile 128(n) x 128(o) ----------------
// grid (16 m-tiles, 8 o-tiles, 32 l), 256 thr, dyn smem = 2*65536
__global__ void __launch_bounds__(256) conv_mma() {
    extern __shared__ char smem[];
    uint32_t sb = smem_u32(smem);
    const int tid = threadIdx.x, wid = tid >> 5, lane = tid & 31;
    const int m0 = blockIdx.x * 128;
    const int ot = blockIdx.y;              // 0..7
    const int l  = blockIdx.z;
    const int br = ot >> 1;
    const int olocal = (ot & 1) * 128;
    const int kb = 2 * br + 1;
    const int sbase = (br == 0) ? 0 : (br == 1) ? 1 : (br == 2) ? 4 : 9;
    const int wm = (wid & 3) * 32, wn = (wid >> 2) * 64;

    // valid taps
    int lsrcs[7], slabs[7], ntap = 0;
    for (int t = 0; t < kb; t++) {
        int lsrc = l + t - br;
        if (lsrc >= 0 && lsrc < L_) { lsrcs[ntap] = lsrc; slabs[ntap] = sbase + t; ntap++; }
    }
    const int C = ntap * 16;

    float acc[2][8][4] = {};

    // chunk c -> (tap = c>>4, kc = c&15)
    {
        const __nv_bfloat16* Ahi = g_hshi + ((size_t)lsrcs[0] * NB + m0) * H_;
        const __nv_bfloat16* Alo = g_hslo + ((size_t)lsrcs[0] * NB + m0) * H_;
        const __nv_bfloat16* Bhi = g_wchi + ((size_t)slabs[0] * QH + olocal) * H_;
        const __nv_bfloat16* Blo = g_wclo + ((size_t)slabs[0] * QH + olocal) * H_;
        issue_tile(sb,         Ahi, tid);
        issue_tile(sb + 16384, Alo, tid);
        issue_tile(sb + 32768, Bhi, tid);
        issue_tile(sb + 49152, Blo, tid);
        CP_COMMIT();
    }
    for (int c = 0; c < C; c++) {
        if (c + 1 < C) {
            int tap = (c + 1) >> 4, kc = (c + 1) & 15;
            const __nv_bfloat16* Ahi = g_hshi + ((size_t)lsrcs[tap] * NB + m0) * H_ + kc * 64;
            const __nv_bfloat16* Alo = g_hslo + ((size_t)lsrcs[tap] * NB + m0) * H_ + kc * 64;
            const __nv_bfloat16* Bhi = g_wchi + ((size_t)slabs[tap] * QH + olocal) * H_ + kc * 64;
            const __nv_bfloat16* Blo = g_wclo + ((size_t)slabs[tap] * QH + olocal) * H_ + kc * 64;
            uint32_t nb = sb + ((c + 1) & 1) * 65536;
            issue_tile(nb,         Ahi, tid);
            issue_tile(nb + 16384, Alo, tid);
            issue_tile(nb + 32768, Bhi, tid);
            issue_tile(nb + 49152, Blo, tid);
            CP_COMMIT();
            CP_WAIT1();
        } else {
            CP_WAIT0();
        }
        __syncthreads();
        mma_chunk(sb + (c & 1) * 65536, wm, wn, lane, acc);
        __syncthreads();
    }

    // epilogue: bias add, write g_y
    const int g = lane >> 2, t4 = (lane & 3) * 2;
#pragma unroll
    for (int mt = 0; mt < 2; mt++)
#pragma unroll
        for (int nt = 0; nt < 8; nt++)
#pragma unroll
            for (int hf = 0; hf < 2; hf++) {
                int r = m0 + wm + mt * 16 + g + hf * 8;
                int c = ot * 128 + wn + nt * 8 + t4;
                float2 bb = *(const float2*)&g_bias[c];
                float2 v;
                v.x = acc[mt][nt][hf * 2 + 0] + bb.x;
                v.y = acc[mt][nt][hf * 2 + 1] + bb.y;
                *(float2*)&g_y[((size_t)l * NB + r) * H_ + c] = v;
            }
}

// ---------------- BN stats: deterministic two-stage reduction ----------------
__global__ void stats_partial() {
    __shared__ float ss[8][32], sq[8][32];
    int tx = threadIdx.x, ty = threadIdx.y;
    int c  = blockIdx.x * 32 + tx;
    int r0 = blockIdx.y * 1024;
    float s = 0.f, q = 0.f;
    for (int r = r0 + ty; r < r0 + 1024; r += 8) {
        float v = g_y[(size_t)r * H_ + c];
        s += v; q += v * v;
    }
    ss[ty][tx] = s; sq[ty][tx] = q;
    __syncthreads();
    if (ty == 0) {
        float S = 0.f, Q = 0.f;
#pragma unroll
        for (int j = 0; j < 8; j++) { S += ss[j][tx]; Q += sq[j][tx]; }
        g_psum  [blockIdx.y * H_ + c] = S;
        g_psumsq[blockIdx.y * H_ + c] = Q;
    }
}

__global__ void finalize_kernel(const float* __restrict__ gamma, const float* __restrict__ beta) {
    int c = blockIdx.x * 256 + threadIdx.x;
    if (c >= H_) return;
    float s = 0.f, q = 0.f;
    for (int p = 0; p < 64; p++) { s += g_psum[p * H_ + c]; q += g_psumsq[p * H_ + c]; }
    const float invM = 1.0f / (float)(NB * L_);
    float mean = s * invM;
    float var  = q * invM - mean * mean;
    float rstd = rsqrtf(var + 1e-5f);
    float sc   = rstd * gamma[c];
    g_scale[c] = sc;
    g_shift[c] = beta[c] - mean * sc;
}

// ---------------- final GEMM (SIMT): out = PReLU(BN(y)) @ Wout + bout ----------------
__global__ void __launch_bounds__(256) out_kernel(const float* __restrict__ Wout,
                                                  const float* __restrict__ bout,
                                                  const float* __restrict__ prelu,
                                                  float* __restrict__ out) {
    __shared__ __align__(16) float As[8][128];
    __shared__ __align__(16) float Bs[8][64];
    const int l  = blockIdx.y;
    const int n0 = blockIdx.x * 128;
    const float pa = *prelu;
    const float* A = g_y + ((size_t)l * NB + n0) * H_;
    const int tid  = threadIdx.x;
    const int arow = tid >> 1, acol = (tid & 1) * 4;
    const int brow = tid >> 5, bcol = (tid & 31) * 2;
    const int ty   = tid >> 4, tx   = tid & 15;
    float acc[8][4] = {};
    for (int k0 = 0; k0 < H_; k0 += 8) {
        float4 av = *(const float4*)(A + (size_t)arow * H_ + k0 + acol);
        float4 sc = *(const float4*)(g_scale + k0 + acol);
        float4 sh = *(const float4*)(g_shift + k0 + acol);
        float v0 = av.x * sc.x + sh.x; v0 = (v0 > 0.f) ? v0 : pa * v0;
        float v1 = av.y * sc.y + sh.y; v1 = (v1 > 0.f) ? v1 : pa * v1;
        float v2 = av.z * sc.z + sh.z; v2 = (v2 > 0.f) ? v2 : pa * v2;
        float v3 = av.w * sc.w + sh.w; v3 = (v3 > 0.f) ? v3 : pa * v3;
        As[acol + 0][arow] = v0; As[acol + 1][arow] = v1;
        As[acol + 2][arow] = v2; As[acol + 3][arow] = v3;
        float2 bv = *(const float2*)(Wout + (size_t)(k0 + brow) * OUT_ + bcol);
        *(float2*)&Bs[brow][bcol] = bv;
        __syncthreads();
#pragma unroll
        for (int kk = 0; kk < 8; kk++) {
            float a[8], b[4];
            ((float4*)a)[0] = *(const float4*)&As[kk][ty * 8];
            ((float4*)a)[1] = *(const float4*)&As[kk][ty * 8 + 4];
            ((float4*)b)[0] = *(const float4*)&Bs[kk][tx * 4];
#pragma unroll
            for (int i = 0; i < 8; i++)
#pragma unroll
                for (int j = 0; j < 4; j++) acc[i][j] += a[i] * b[j];
        }
        __syncthreads();
    }
    const int o0 = tx * 4;
    float4 bb = *(const float4*)(bout + o0);
#pragma unroll
    for (int i = 0; i < 8; i++) {
        int n = n0 + ty * 8 + i;
        float4 v;
        v.x = acc[i][0] + bb.x; v.y = acc[i][1] + bb.y;
        v.z = acc[i][2] + bb.z; v.w = acc[i][3] + bb.w;
        *(float4*)&out[((size_t)n * L_ + l) * OUT_ + o0] = v;
    }
}

// ---------------- launch ----------------
#define MMA_SMEM (2 * 65536)

extern "C" void kernel_launch(void* const* d_in, const int* in_sizes, int n_in,
                              void* d_out, int out_size)
{
    const float* hwa   = (const float*)d_in[0];
    const float* Wx    = (const float*)d_in[1];
    const float* bx    = (const float*)d_in[2];
    const float* Wh    = (const float*)d_in[3];
    const float* bh    = (const float*)d_in[4];
    const float* w1    = (const float*)d_in[5];
    const float* b1    = (const float*)d_in[6];
    const float* w3    = (const float*)d_in[7];
    const float* b3    = (const float*)d_in[8];
    const float* w5    = (const float*)d_in[9];
    const float* b5    = (const float*)d_in[10];
    const float* w7    = (const float*)d_in[11];
    const float* b7    = (const float*)d_in[12];
    const float* gamma = (const float*)d_in[13];
    const float* beta  = (const float*)d_in[14];
    const float* prelu = (const float*)d_in[15];
    const float* Wout  = (const float*)d_in[16];
    const float* bout  = (const float*)d_in[17];
    float* out = (float*)d_out;

    cudaFuncSetAttribute(rnn_mma,  cudaFuncAttributeMaxDynamicSharedMemorySize, MMA_SMEM);
    cudaFuncSetAttribute(conv_mma, cudaFuncAttributeMaxDynamicSharedMemorySize, MMA_SMEM);

    prep_wh<<<(H_ * H_) / 256, 256>>>(Wh);
    prep_wc<<<(16 * QH * H_) / 256, 256>>>(w1, b1, w3, b3, w5, b5, w7, b7);
    xr_kernel<<<dim3(H_ / 64, NB / 128), 256>>>(hwa, Wx, bx);
    step0_kernel<<<(NB * H_) / 256, 256>>>(bh);
    for (int l = 1; l < L_; l++)
        rnn_mma<<<dim3(H_ / 128, NB / 128), 256, MMA_SMEM>>>(bh, l);
    conv_mma<<<dim3(NB / 128, 8, L_), 256, MMA_SMEM>>>();
    stats_partial<<<dim3(H_ / 32, 64), dim3(32, 8)>>>();
    finalize_kernel<<<(H_ + 255) / 256, 256>>>(gamma, beta);
    out_kernel<<<dim3(NB / 128, L_), 256>>>(Wout, bout, prelu, out);
}

// round 12
// speedup vs baseline: 3.0676x; 1.0452x over previous
#include <cuda_runtime.h>
#include <cuda_bf16.h>
#include <math.h>
#include <stdint.h>

// ---------------- problem dims ----------------
#define NB   2048    // E*S
#define IN_  2048
#define H_   1024
#define L_   32
#define OUT_ 64
#define QH   256     // H/4 per-branch out channels

// ---------------- scratch (device globals; no allocation allowed) ----------------
__device__ __align__(128) float          g_xr  [(size_t)NB * H_];          // 8 MB
__device__ __align__(128) __nv_bfloat16  g_hshi[(size_t)L_ * NB * H_];     // 128 MB [l][n][h]
__device__ __align__(128) __nv_bfloat16  g_hslo[(size_t)L_ * NB * H_];     // 128 MB
__device__ __align__(128) float          g_y   [(size_t)L_ * NB * H_];     // 256 MB [l][n][c]
__device__ __align__(128) __nv_bfloat16  g_whhi[(size_t)H_ * H_];          // WhT [n][k]
__device__ __align__(128) __nv_bfloat16  g_whlo[(size_t)H_ * H_];
__device__ __align__(128) __nv_bfloat16  g_wchi[(size_t)16 * QH * H_];     // [slab][o][k]
__device__ __align__(128) __nv_bfloat16  g_wclo[(size_t)16 * QH * H_];
__device__ float g_bias[H_];
__device__ float g_psum [64 * H_];
__device__ float g_psumsq[64 * H_];
__device__ float g_scale[H_];
__device__ float g_shift[H_];

// ---------------- helpers ----------------
__device__ __forceinline__ uint32_t smem_u32(const void* p) {
    uint32_t a;
    asm("{ .reg .u64 t; cvta.to.shared.u64 t, %1; cvt.u32.u64 %0, t; }" : "=r"(a) : "l"(p));
    return a;
}

#define CP16(dst, src) \
    asm volatile("cp.async.cg.shared.global [%0], [%1], 16;" :: "r"(dst), "l"(src))
#define CP_COMMIT() asm volatile("cp.async.commit_group;")
#define CP_WAIT1()  asm volatile("cp.async.wait_group 1;")
#define CP_WAIT0()  asm volatile("cp.async.wait_group 0;")

#define LDSM4(r0, r1, r2, r3, addr)                                          \
    asm volatile("ldmatrix.sync.aligned.m8n8.x4.shared.b16 {%0,%1,%2,%3}, [%4];" \
        : "=r"(r0), "=r"(r1), "=r"(r2), "=r"(r3) : "r"(addr))

#define MMA_BF16(d, a, b)                                                     \
    asm volatile("mma.sync.aligned.m16n8k16.row.col.f32.bf16.bf16.f32 "       \
        "{%0,%1,%2,%3}, {%4,%5,%6,%7}, {%8,%9}, {%0,%1,%2,%3};"               \
        : "+f"((d)[0]), "+f"((d)[1]), "+f"((d)[2]), "+f"((d)[3])              \
        : "r"((a)[0]), "r"((a)[1]), "r"((a)[2]), "r"((a)[3]),                 \
          "r"((b)[0]), "r"((b)[1]))

__device__ __forceinline__ void split_bf16(float x, __nv_bfloat16& hi, __nv_bfloat16& lo) {
    hi = __float2bfloat16(x);
    lo = __float2bfloat16(x - __bfloat162float(hi));
}

// issue one ROWSx64 bf16 tile (row stride H_) into XOR-swizzled smem via cp.async
template<int ROWS>
__device__ __forceinline__ void issue_tile(uint32_t dst, const __nv_bfloat16* __restrict__ src, int tid) {
#pragma unroll
    for (int i = 0; i < ROWS / 32; i++) {
        int u = tid + 256 * i;
        int r = u >> 3, cu = u & 7;
        uint32_t sw = (uint32_t)(r * 128) + (uint32_t)(((cu ^ (r & 7)) << 4));
        CP16(dst + sw, (const void*)(src + (size_t)r * H_ + cu * 8));
    }
}

// ---------------- weight prep ----------------
__global__ void prep_wh(const float* __restrict__ Wh) {
    int idx = blockIdx.x * 256 + threadIdx.x;      // over H*H, [n][k]
    int n = idx >> 10, k = idx & 1023;
    float w = Wh[(size_t)k * H_ + n];
    __nv_bfloat16 hi, lo; split_bf16(w, hi, lo);
    g_whhi[idx] = hi; g_whlo[idx] = lo;
}

__global__ void prep_wc(const float* __restrict__ w1, const float* __restrict__ b1,
                        const float* __restrict__ w3, const float* __restrict__ b3,
                        const float* __restrict__ w5, const float* __restrict__ b5,
                        const float* __restrict__ w7, const float* __restrict__ b7) {
    int idx = blockIdx.x * 256 + threadIdx.x;      // over 16*QH*H_, [s][o][k]
    int s   = idx / (QH * H_);
    int rem = idx - s * (QH * H_);
    int o   = rem >> 10;
    int k   = rem & 1023;
    int b, t;
    if (s == 0)      { b = 0; t = 0;     }
    else if (s < 4)  { b = 1; t = s - 1; }
    else if (s < 9)  { b = 2; t = s - 4; }
    else             { b = 3; t = s - 9; }
    const float* w = (b == 0) ? w1 : (b == 1) ? w3 : (b == 2) ? w5 : w7;
    int kb = 2 * b + 1;
    float val = w[((size_t)o * H_ + k) * kb + t];
    __nv_bfloat16 hi, lo; split_bf16(val, hi, lo);
    g_wchi[idx] = hi; g_wclo[idx] = lo;
    if (idx < H_) {
        int bb = idx >> 8, oo = idx & 255;
        const float* bp = (bb == 0) ? b1 : (bb == 1) ? b3 : (bb == 2) ? b5 : b7;
        g_bias[idx] = bp[oo];
    }
}

// ---------------- GEMM 1 (SIMT fp32): x_r = hwa @ Wx + bx ----------------
__global__ void __launch_bounds__(256) xr_kernel(const float* __restrict__ A,
                                                 const float* __restrict__ Bm,
                                                 const float* __restrict__ bx) {
    __shared__ __align__(16) float As[8][128];
    __shared__ __align__(16) float Bs[8][64];
    const int m0 = blockIdx.y * 128, n0 = blockIdx.x * 64;
    const int tid  = threadIdx.x;
    const int arow = tid >> 1, acol = (tid & 1) * 4;
    const int brow = tid >> 5, bcol = (tid & 31) * 2;
    const int ty   = tid >> 4, tx   = tid & 15;
    float acc[8][4] = {};
    for (int k0 = 0; k0 < IN_; k0 += 8) {
        float4 av = *(const float4*)(A + (size_t)(m0 + arow) * IN_ + k0 + acol);
        float2 bv = *(const float2*)(Bm + (size_t)(k0 + brow) * H_ + n0 + bcol);
        As[acol + 0][arow] = av.x; As[acol + 1][arow] = av.y;
        As[acol + 2][arow] = av.z; As[acol + 3][arow] = av.w;
        *(float2*)&Bs[brow][bcol] = bv;
        __syncthreads();
#pragma unroll
        for (int kk = 0; kk < 8; kk++) {
            float a[8], b[4];
            ((float4*)a)[0] = *(const float4*)&As[kk][ty * 8];
            ((float4*)a)[1] = *(const float4*)&As[kk][ty * 8 + 4];
            ((float4*)b)[0] = *(const float4*)&Bs[kk][tx * 4];
#pragma unroll
            for (int i = 0; i < 8; i++)
#pragma unroll
                for (int j = 0; j < 4; j++) acc[i][j] += a[i] * b[j];
        }
        __syncthreads();
    }
    const int c0 = n0 + tx * 4;
    float4 bb = *(const float4*)(bx + c0);
#pragma unroll
    for (int i = 0; i < 8; i++) {
        int r = m0 + ty * 8 + i;
        float4 v;
        v.x = acc[i][0] + bb.x; v.y = acc[i][1] + bb.y;
        v.z = acc[i][2] + bb.z; v.w = acc[i][3] + bb.w;
        *(float4*)&g_xr[(size_t)r * H_ + c0] = v;
    }
}

// ---------------- step 0: hs[0] = 0.5*tanh(x_r + bh), split bf16 ----------------
__global__ void step0_kernel(const float* __restrict__ bh) {
    int i = blockIdx.x * 256 + threadIdx.x;
    int c = i & (H_ - 1);
    float v = 0.5f * tanhf(g_xr[i] + bh[c]);
    __nv_bfloat16 hi, lo; split_bf16(v, hi, lo);
    g_hshi[i] = hi; g_hslo[i] = lo;
}

// ---------------- RNN step (HMMA): hs[l] = 0.5*hs[l-1] + 0.5*tanh(xr + hs[l-1]@Wh + bh) ----------------
// grid (8 n-tiles, 16 m-tiles), 256 thr, dyn smem = 2*65536
__global__ void __launch_bounds__(256) rnn_mma(const float* __restrict__ bh, int l) {
    extern __shared__ char smem[];
    uint32_t sb = smem_u32(smem);
    const int tid = threadIdx.x, wid = tid >> 5, lane = tid & 31;
    const int n0 = blockIdx.x * 128, m0 = blockIdx.y * 128;
    const int wm = (wid & 3) * 32, wn = (wid >> 2) * 64;

    const __nv_bfloat16* Ahi = g_hshi + ((size_t)(l - 1) * NB + m0) * H_;
    const __nv_bfloat16* Alo = g_hslo + ((size_t)(l - 1) * NB + m0) * H_;
    const __nv_bfloat16* Bhi = g_whhi + (size_t)n0 * H_;
    const __nv_bfloat16* Blo = g_whlo + (size_t)n0 * H_;

    float acc[2][8][4] = {};

    // prologue: chunk 0 -> buf0
    issue_tile<128>(sb,         Ahi, tid);
    issue_tile<128>(sb + 16384, Alo, tid);
    issue_tile<128>(sb + 32768, Bhi, tid);
    issue_tile<128>(sb + 49152, Blo, tid);
    CP_COMMIT();

    for (int c = 0; c < 16; c++) {
        if (c < 15) {
            uint32_t nb = sb + ((c + 1) & 1) * 65536;
            int off = (c + 1) * 64;
            issue_tile<128>(nb,         Ahi + off, tid);
            issue_tile<128>(nb + 16384, Alo + off, tid);
            issue_tile<128>(nb + 32768, Bhi + off, tid);
            issue_tile<128>(nb + 49152, Blo + off, tid);
            CP_COMMIT();
            CP_WAIT1();
        } else {
            CP_WAIT0();
        }
        __syncthreads();
        {
            uint32_t buf = sb + (c & 1) * 65536;
            const uint32_t pAhi = buf, pAlo = buf + 16384, pBhi = buf + 32768, pBlo = buf + 49152;
#pragma unroll
            for (int ks = 0; ks < 4; ks++) {
                uint32_t a[2][2][4];
                const int arow0 = wm + (lane & 7) + ((lane >> 3) & 1) * 8;
                const int acu   = 2 * ks + (lane >> 4);
#pragma unroll
                for (int mt = 0; mt < 2; mt++) {
                    int r = arow0 + mt * 16;
                    uint32_t off = (uint32_t)(r * 128 + ((acu ^ (r & 7)) << 4));
                    LDSM4(a[0][mt][0], a[0][mt][1], a[0][mt][2], a[0][mt][3], pAhi + off);
                    LDSM4(a[1][mt][0], a[1][mt][1], a[1][mt][2], a[1][mt][3], pAlo + off);
                }
                uint32_t b[2][8][2];
                const int brow0 = wn + (lane & 7) + ((lane >> 4) & 1) * 8;
                const int bcu   = 2 * ks + ((lane >> 3) & 1);
#pragma unroll
                for (int p = 0; p < 4; p++) {
                    int r = brow0 + p * 16;
                    uint32_t off = (uint32_t)(r * 128 + ((bcu ^ (r & 7)) << 4));
                    uint32_t r0, r1, r2, r3;
                    LDSM4(r0, r1, r2, r3, pBhi + off);
                    b[0][2*p][0] = r0; b[0][2*p][1] = r1; b[0][2*p+1][0] = r2; b[0][2*p+1][1] = r3;
                    LDSM4(r0, r1, r2, r3, pBlo + off);
                    b[1][2*p][0] = r0; b[1][2*p][1] = r1; b[1][2*p+1][0] = r2; b[1][2*p+1][1] = r3;
                }
                // term-major: same-acc MMAs are 16 instructions apart (hide HMMA latency)
#pragma unroll
                for (int mt = 0; mt < 2; mt++)
#pragma unroll
                    for (int nt = 0; nt < 8; nt++) MMA_BF16(acc[mt][nt], a[0][mt], b[0][nt]);
#pragma unroll
                for (int mt = 0; mt < 2; mt++)
#pragma unroll
                    for (int nt = 0; nt < 8; nt++) MMA_BF16(acc[mt][nt], a[1][mt], b[0][nt]);
#pragma unroll
                for (int mt = 0; mt < 2; mt++)
#pragma unroll
                    for (int nt = 0; nt < 8; nt++) MMA_BF16(acc[mt][nt], a[0][mt], b[1][nt]);
            }
        }
        __syncthreads();
    }

    // epilogue: fused leaky-tanh + re-split
    const int g = lane >> 2, t4 = (lane & 3) * 2;
    const size_t prevB = (size_t)(l - 1) * NB * H_;
    const size_t curB  = (size_t)l * NB * H_;
#pragma unroll
    for (int mt = 0; mt < 2; mt++)
#pragma unroll
        for (int nt = 0; nt < 8; nt++)
#pragma unroll
            for (int hf = 0; hf < 2; hf++) {
                int r = m0 + wm + mt * 16 + g + hf * 8;
                int c = n0 + wn + nt * 8 + t4;
                size_t base = (size_t)r * H_ + c;
                float ax = acc[mt][nt][hf * 2 + 0];
                float ay = acc[mt][nt][hf * 2 + 1];
                float2 xr2 = *(const float2*)&g_xr[base];
                float2 bh2 = *(const float2*)&bh[c];
                __nv_bfloat162 ph = *(const __nv_bfloat162*)&g_hshi[prevB + base];
                __nv_bfloat162 pl = *(const __nv_bfloat162*)&g_hslo[prevB + base];
                float hp0 = __bfloat162float(ph.x) + __bfloat162float(pl.x);
                float hp1 = __bfloat162float(ph.y) + __bfloat162float(pl.y);
                float h0 = 0.5f * hp0 + 0.5f * tanhf(xr2.x + ax + bh2.x);
                float h1 = 0.5f * hp1 + 0.5f * tanhf(xr2.y + ay + bh2.y);
                __nv_bfloat162 vh, vl;
                __nv_bfloat16 hh, hl;
                split_bf16(h0, hh, hl); vh.x = hh; vl.x = hl;
                split_bf16(h1, hh, hl); vh.y = hh; vl.y = hl;
                *(__nv_bfloat162*)&g_hshi[curB + base] = vh;
                *(__nv_bfloat162*)&g_hslo[curB + base] = vl;
            }
}

// ---------------- conv (HMMA): tap-decomposed GEMM, CTA tile 128(n) x 256(branch) ----------------
// grid (16 m-tiles, 4 branches, 32 l), 256 thr, warp tile 64x64, dyn smem = 2*98304
__global__ void __launch_bounds__(256, 1) conv_mma() {
    extern __shared__ char smem[];
    uint32_t sb = smem_u32(smem);
    const int tid = threadIdx.x, wid = tid >> 5, lane = tid & 31;
    const int m0 = blockIdx.x * 128;
    const int br = blockIdx.y;              // 0..3
    const int l  = blockIdx.z;
    const int kb = 2 * br + 1;
    const int sbase = (br == 0) ? 0 : (br == 1) ? 1 : (br == 2) ? 4 : 9;
    const int wm = (wid & 1) * 64, wn = (wid >> 1) * 64;

    // valid taps
    int lsrcs[7], slabs[7], ntap = 0;
    for (int t = 0; t < kb; t++) {
        int lsrc = l + t - br;
        if (lsrc >= 0 && lsrc < L_) { lsrcs[ntap] = lsrc; slabs[ntap] = sbase + t; ntap++; }
    }
    const int C = ntap * 16;

    float acc[4][8][4] = {};

    // buffer layout: [Ahi 16K][Alo 16K][Bhi 32K][Blo 32K] = 96K, x2
    {
        const __nv_bfloat16* Ahi = g_hshi + ((size_t)lsrcs[0] * NB + m0) * H_;
        const __nv_bfloat16* Alo = g_hslo + ((size_t)lsrcs[0] * NB + m0) * H_;
        const __nv_bfloat16* Bhi = g_wchi + (size_t)slabs[0] * QH * H_;
        const __nv_bfloat16* Blo = g_wclo + (size_t)slabs[0] * QH * H_;
        issue_tile<128>(sb,         Ahi, tid);
        issue_tile<128>(sb + 16384, Alo, tid);
        issue_tile<256>(sb + 32768, Bhi, tid);
        issue_tile<256>(sb + 65536, Blo, tid);
        CP_COMMIT();
    }
    for (int c = 0; c < C; c++) {
        if (c + 1 < C) {
            int tap = (c + 1) >> 4, kc = (c + 1) & 15;
            const __nv_bfloat16* Ahi = g_hshi + ((size_t)lsrcs[tap] * NB + m0) * H_ + kc * 64;
            const __nv_bfloat16* Alo = g_hslo + ((size_t)lsrcs[tap] * NB + m0) * H_ + kc * 64;
            const __nv_bfloat16* Bhi = g_wchi + (size_t)slabs[tap] * QH * H_ + kc * 64;
            const __nv_bfloat16* Blo = g_wclo + (size_t)slabs[tap] * QH * H_ + kc * 64;
            uint32_t nb = sb + ((c + 1) & 1) * 98304;
            issue_tile<128>(nb,         Ahi, tid);
            issue_tile<128>(nb + 16384, Alo, tid);
            issue_tile<256>(nb + 32768, Bhi, tid);
            issue_tile<256>(nb + 65536, Blo, tid);
            CP_COMMIT();
            CP_WAIT1();
        } else {
            CP_WAIT0();
        }
        __syncthreads();
        {
            uint32_t buf = sb + (c & 1) * 98304;
            const uint32_t pAhi = buf, pAlo = buf + 16384, pBhi = buf + 32768, pBlo = buf + 65536;
#pragma unroll
            for (int ks = 0; ks < 4; ks++) {
                uint32_t ah[4][4], al[4][4];
                const int arow0 = wm + (lane & 7) + ((lane >> 3) & 1) * 8;
                const int acu   = 2 * ks + (lane >> 4);
#pragma unroll
                for (int mt = 0; mt < 4; mt++) {
                    int r = arow0 + mt * 16;
                    uint32_t off = (uint32_t)(r * 128 + ((acu ^ (r & 7)) << 4));
                    LDSM4(ah[mt][0], ah[mt][1], ah[mt][2], ah[mt][3], pAhi + off);
                    LDSM4(al[mt][0], al[mt][1], al[mt][2], al[mt][3], pAlo + off);
                }
                uint32_t b[8][2];
                const int brow0 = wn + (lane & 7) + ((lane >> 4) & 1) * 8;
                const int bcu   = 2 * ks + ((lane >> 3) & 1);
#pragma unroll
                for (int p = 0; p < 4; p++) {
                    int r = brow0 + p * 16;
                    uint32_t off = (uint32_t)(r * 128 + ((bcu ^ (r & 7)) << 4));
                    uint32_t r0, r1, r2, r3;
                    LDSM4(r0, r1, r2, r3, pBhi + off);
                    b[2*p][0] = r0; b[2*p][1] = r1; b[2*p+1][0] = r2; b[2*p+1][1] = r3;
                }
                // term 1: Ahi * Bhi    term 2: Alo * Bhi   (term-major ordering)
#pragma unroll
                for (int mt = 0; mt < 4; mt++)
#pragma unroll
                    for (int nt = 0; nt < 8; nt++) MMA_BF16(acc[mt][nt], ah[mt], b[nt]);
#pragma unroll
                for (int mt = 0; mt < 4; mt++)
#pragma unroll
                    for (int nt = 0; nt < 8; nt++) MMA_BF16(acc[mt][nt], al[mt], b[nt]);
                // reload b with Blo, term 3: Ahi * Blo
#pragma unroll
                for (int p = 0; p < 4; p++) {
                    int r = brow0 + p * 16;
                    uint32_t off = (uint32_t)(r * 128 + ((bcu ^ (r & 7)) << 4));
                    uint32_t r0, r1, r2, r3;
                    LDSM4(r0, r1, r2, r3, pBlo + off);
                    b[2*p][0] = r0; b[2*p][1] = r1; b[2*p+1][0] = r2; b[2*p+1][1] = r3;
                }
#pragma unroll
                for (int mt = 0; mt < 4; mt++)
#pragma unroll
                    for (int nt = 0; nt < 8; nt++) MMA_BF16(acc[mt][nt], ah[mt], b[nt]);
            }
        }
        __syncthreads();
    }

    // epilogue: bias add, write g_y
    const int g = lane >> 2, t4 = (lane & 3) * 2;
#pragma unroll
    for (int mt = 0; mt < 4; mt++)
#pragma unroll
        for (int nt = 0; nt < 8; nt++)
#pragma unroll
            for (int hf = 0; hf < 2; hf++) {
                int r = m0 + wm + mt * 16 + g + hf * 8;
                int c = br * 256 + wn + nt * 8 + t4;
                float2 bb = *(const float2*)&g_bias[c];
                float2 v;
                v.x = acc[mt][nt][hf * 2 + 0] + bb.x;
                v.y = acc[mt][nt][hf * 2 + 1] + bb.y;
                *(float2*)&g_y[((size_t)l * NB + r) * H_ + c] = v;
            }
}

// ---------------- BN stats: deterministic two-stage reduction ----------------
__global__ void stats_partial() {
    __shared__ float ss[8][32], sq[8][32];
    int tx = threadIdx.x, ty = threadIdx.y;
    int c  = blockIdx.x * 32 + tx;
    int r0 = blockIdx.y * 1024;
    float s = 0.f, q = 0.f;
    for (int r = r0 + ty; r < r0 + 1024; r += 8) {
        float v = g_y[(size_t)r * H_ + c];
        s += v; q += v * v;
    }
    ss[ty][tx] = s; sq[ty][tx] = q;
    __syncthreads();
    if (ty == 0) {
        float S = 0.f, Q = 0.f;
#pragma unroll
        for (int j = 0; j < 8; j++) { S += ss[j][tx]; Q += sq[j][tx]; }
        g_psum  [blockIdx.y * H_ + c] = S;
        g_psumsq[blockIdx.y * H_ + c] = Q;
    }
}

__global__ void finalize_kernel(const float* __restrict__ gamma, const float* __restrict__ beta) {
    int c = blockIdx.x * 256 + threadIdx.x;
    if (c >= H_) return;
    float s = 0.f, q = 0.f;
    for (int p = 0; p < 64; p++) { s += g_psum[p * H_ + c]; q += g_psumsq[p * H_ + c]; }
    const float invM = 1.0f / (float)(NB * L_);
    float mean = s * invM;
    float var  = q * invM - mean * mean;
    float rstd = rsqrtf(var + 1e-5f);
    float sc   = rstd * gamma[c];
    g_scale[c] = sc;
    g_shift[c] = beta[c] - mean * sc;
}

// ---------------- final GEMM (SIMT): out = PReLU(BN(y)) @ Wout + bout ----------------
__global__ void __launch_bounds__(256) out_kernel(const float* __restrict__ Wout,
                                                  const float* __restrict__ bout,
                                                  const float* __restrict__ prelu,
                                                  float* __restrict__ out) {
    __shared__ __align__(16) float As[8][128];
    __shared__ __align__(16) float Bs[8][64];
    const int l  = blockIdx.y;
    const int n0 = blockIdx.x * 128;
    const float pa = *prelu;
    const float* A = g_y + ((size_t)l * NB + n0) * H_;
    const int tid  = threadIdx.x;
    const int arow = tid >> 1, acol = (tid & 1) * 4;
    const int brow = tid >> 5, bcol = (tid & 31) * 2;
    const int ty   = tid >> 4, tx   = tid & 15;
    float acc[8][4] = {};
    for (int k0 = 0; k0 < H_; k0 += 8) {
        float4 av = *(const float4*)(A + (size_t)arow * H_ + k0 + acol);
        float4 sc = *(const float4*)(g_scale + k0 + acol);
        float4 sh = *(const float4*)(g_shift + k0 + acol);
        float v0 = av.x * sc.x + sh.x; v0 = (v0 > 0.f) ? v0 : pa * v0;
        float v1 = av.y * sc.y + sh.y; v1 = (v1 > 0.f) ? v1 : pa * v1;
        float v2 = av.z * sc.z + sh.z; v2 = (v2 > 0.f) ? v2 : pa * v2;
        float v3 = av.w * sc.w + sh.w; v3 = (v3 > 0.f) ? v3 : pa * v3;
        As[acol + 0][arow] = v0; As[acol + 1][arow] = v1;
        As[acol + 2][arow] = v2; As[acol + 3][arow] = v3;
        float2 bv = *(const float2*)(Wout + (size_t)(k0 + brow) * OUT_ + bcol);
        *(float2*)&Bs[brow][bcol] = bv;
        __syncthreads();
#pragma unroll
        for (int kk = 0; kk < 8; kk++) {
            float a[8], b[4];
            ((float4*)a)[0] = *(const float4*)&As[kk][ty * 8];
            ((float4*)a)[1] = *(const float4*)&As[kk][ty * 8 + 4];
            ((float4*)b)[0] = *(const float4*)&Bs[kk][tx * 4];
#pragma unroll
            for (int i = 0; i < 8; i++)
#pragma unroll
                for (int j = 0; j < 4; j++) acc[i][j] += a[i] * b[j];
        }
        __syncthreads();
    }
    const int o0 = tx * 4;
    float4 bb = *(const float4*)(bout + o0);
#pragma unroll
    for (int i = 0; i < 8; i++) {
        int n = n0 + ty * 8 + i;
        float4 v;
        v.x = acc[i][0] + bb.x; v.y = acc[i][1] + bb.y;
        v.z = acc[i][2] + bb.z; v.w = acc[i][3] + bb.w;
        *(float4*)&out[((size_t)n * L_ + l) * OUT_ + o0] = v;
    }
}

// ---------------- launch ----------------
#define RNN_SMEM  (2 * 65536)
#define CONV_SMEM (2 * 98304)

extern "C" void kernel_launch(void* const* d_in, const int* in_sizes, int n_in,
                              void* d_out, int out_size)
{
    const float* hwa   = (const float*)d_in[0];
    const float* Wx    = (const float*)d_in[1];
    const float* bx    = (const float*)d_in[2];
    const float* Wh    = (const float*)d_in[3];
    const float* bh    = (const float*)d_in[4];
    const float* w1    = (const float*)d_in[5];
    const float* b1    = (const float*)d_in[6];
    const float* w3    = (const float*)d_in[7];
    const float* b3    = (const float*)d_in[8];
    const float* w5    = (const float*)d_in[9];
    const float* b5    = (const float*)d_in[10];
    const float* w7    = (const float*)d_in[11];
    const float* b7    = (const float*)d_in[12];
    const float* gamma = (const float*)d_in[13];
    const float* beta  = (const float*)d_in[14];
    const float* prelu = (const float*)d_in[15];
    const float* Wout  = (const float*)d_in[16];
    const float* bout  = (const float*)d_in[17];
    float* out = (float*)d_out;

    cudaFuncSetAttribute(rnn_mma,  cudaFuncAttributeMaxDynamicSharedMemorySize, RNN_SMEM);
    cudaFuncSetAttribute(conv_mma, cudaFuncAttributeMaxDynamicSharedMemorySize, CONV_SMEM);

    prep_wh<<<(H_ * H_) / 256, 256>>>(Wh);
    prep_wc<<<(16 * QH * H_) / 256, 256>>>(w1, b1, w3, b3, w5, b5, w7, b7);
    xr_kernel<<<dim3(H_ / 64, NB / 128), 256>>>(hwa, Wx, bx);
    step0_kernel<<<(NB * H_) / 256, 256>>>(bh);
    for (int l = 1; l < L_; l++)
        rnn_mma<<<dim3(H_ / 128, NB / 128), 256, RNN_SMEM>>>(bh, l);
    conv_mma<<<dim3(NB / 128, 4, L_), 256, CONV_SMEM>>>();
    stats_partial<<<dim3(H_ / 32, 64), dim3(32, 8)>>>();
    finalize_kernel<<<(H_ + 255) / 256, 256>>>(gamma, beta);
    out_kernel<<<dim3(NB / 128, L_), 256>>>(Wout, bout, prelu, out);
}

// round 14
// speedup vs baseline: 3.1654x; 1.0319x over previous
#include <cuda_runtime.h>
#include <cuda_bf16.h>
#include <math.h>
#include <stdint.h>

// ---------------- problem dims ----------------
#define NB   2048    // E*S
#define IN_  2048
#define H_   1024
#define L_   32
#define OUT_ 64
#define QH   256     // H/4 per-branch out channels

// ---------------- scratch (device globals; no allocation allowed) ----------------
__device__ __align__(128) float          g_xr  [(size_t)NB * H_];          // 8 MB
__device__ __align__(128) __nv_bfloat16  g_hshi[(size_t)L_ * NB * H_];     // 128 MB [l][n][h]
__device__ __align__(128) __nv_bfloat16  g_hslo[(size_t)L_ * NB * H_];     // 128 MB
__device__ __align__(128) __nv_bfloat16  g_yhi [(size_t)L_ * NB * H_];     // 128 MB [l][n][c]
__device__ __align__(128) __nv_bfloat16  g_ylo [(size_t)L_ * NB * H_];     // 128 MB
__device__ __align__(128) __nv_bfloat16  g_whhi[(size_t)H_ * H_];          // WhT [n][k]
__device__ __align__(128) __nv_bfloat16  g_whlo[(size_t)H_ * H_];
__device__ __align__(128) __nv_bfloat16  g_wchi[(size_t)16 * QH * H_];     // [slab][o][k]
__device__ __align__(128) __nv_bfloat16  g_wclo[(size_t)16 * QH * H_];
__device__ __align__(128) __nv_bfloat16  g_ahi [(size_t)NB * IN_];         // hwa split
__device__ __align__(128) __nv_bfloat16  g_alo [(size_t)NB * IN_];
__device__ __align__(128) __nv_bfloat16  g_wxhi[(size_t)H_ * IN_];         // WxT [n][k]
__device__ __align__(128) __nv_bfloat16  g_wxlo[(size_t)H_ * IN_];
__device__ __align__(128) __nv_bfloat16  g_wohi[(size_t)OUT_ * H_];        // WoutT [o][k]
__device__ __align__(128) __nv_bfloat16  g_wolo[(size_t)OUT_ * H_];
__device__ float g_bias[H_];
__device__ float g_psum [64 * H_];
__device__ float g_psumsq[64 * H_];
__device__ float g_scale[H_];
__device__ float g_shift[H_];

// ---------------- helpers ----------------
__device__ __forceinline__ uint32_t smem_u32(const void* p) {
    uint32_t a;
    asm("{ .reg .u64 t; cvta.to.shared.u64 t, %1; cvt.u32.u64 %0, t; }" : "=r"(a) : "l"(p));
    return a;
}

#define CP16(dst, src) \
    asm volatile("cp.async.cg.shared.global [%0], [%1], 16;" :: "r"(dst), "l"(src))
#define CP_COMMIT() asm volatile("cp.async.commit_group;")
#define CP_WAIT1()  asm volatile("cp.async.wait_group 1;")
#define CP_WAIT0()  asm volatile("cp.async.wait_group 0;")

#define LDSM4(r0, r1, r2, r3, addr)                                          \
    asm volatile("ldmatrix.sync.aligned.m8n8.x4.shared.b16 {%0,%1,%2,%3}, [%4];" \
        : "=r"(r0), "=r"(r1), "=r"(r2), "=r"(r3) : "r"(addr))

#define MMA_BF16(d, a, b)                                                     \
    asm volatile("mma.sync.aligned.m16n8k16.row.col.f32.bf16.bf16.f32 "       \
        "{%0,%1,%2,%3}, {%4,%5,%6,%7}, {%8,%9}, {%0,%1,%2,%3};"               \
        : "+f"((d)[0]), "+f"((d)[1]), "+f"((d)[2]), "+f"((d)[3])              \
        : "r"((a)[0]), "r"((a)[1]), "r"((a)[2]), "r"((a)[3]),                 \
          "r"((b)[0]), "r"((b)[1]))

__device__ __forceinline__ void split_bf16(float x, __nv_bfloat16& hi, __nv_bfloat16& lo) {
    hi = __float2bfloat16(x);
    lo = __float2bfloat16(x - __bfloat162float(hi));
}

// issue one ROWSx64 bf16 tile (row stride STRIDE elems) into XOR-swizzled smem via cp.async
template<int ROWS, int STRIDE>
__device__ __forceinline__ void issue_tile(uint32_t dst, const __nv_bfloat16* __restrict__ src, int tid) {
#pragma unroll
    for (int i = 0; i < ROWS / 32; i++) {
        int u = tid + 256 * i;
        int r = u >> 3, cu = u & 7;
        uint32_t sw = (uint32_t)(r * 128) + (uint32_t)(((cu ^ (r & 7)) << 4));
        CP16(dst + sw, (const void*)(src + (size_t)r * STRIDE + cu * 8));
    }
}

// ---------------- prep kernels ----------------
__global__ void prep_wh(const float* __restrict__ Wh) {
    int idx = blockIdx.x * 256 + threadIdx.x;      // H*H, [n][k]
    int n = idx >> 10, k = idx & 1023;
    float w = Wh[(size_t)k * H_ + n];
    __nv_bfloat16 hi, lo; split_bf16(w, hi, lo);
    g_whhi[idx] = hi; g_whlo[idx] = lo;
}

__global__ void prep_wc(const float* __restrict__ w1, const float* __restrict__ b1,
                        const float* __restrict__ w3, const float* __restrict__ b3,
                        const float* __restrict__ w5, const float* __restrict__ b5,
                        const float* __restrict__ w7, const float* __restrict__ b7) {
    int idx = blockIdx.x * 256 + threadIdx.x;      // 16*QH*H_, [s][o][k]
    int s   = idx / (QH * H_);
    int rem = idx - s * (QH * H_);
    int o   = rem >> 10;
    int k   = rem & 1023;
    int b, t;
    if (s == 0)      { b = 0; t = 0;     }
    else if (s < 4)  { b = 1; t = s - 1; }
    else if (s < 9)  { b = 2; t = s - 4; }
    else             { b = 3; t = s - 9; }
    const float* w = (b == 0) ? w1 : (b == 1) ? w3 : (b == 2) ? w5 : w7;
    int kb = 2 * b + 1;
    float val = w[((size_t)o * H_ + k) * kb + t];
    __nv_bfloat16 hi, lo; split_bf16(val, hi, lo);
    g_wchi[idx] = hi; g_wclo[idx] = lo;
    if (idx < H_) {
        int bb = idx >> 8, oo = idx & 255;
        const float* bp = (bb == 0) ? b1 : (bb == 1) ? b3 : (bb == 2) ? b5 : b7;
        g_bias[idx] = bp[oo];
    }
}

__global__ void prep_hwa(const float* __restrict__ hwa) {
    int idx = blockIdx.x * 256 + threadIdx.x;      // NB*IN_
    __nv_bfloat16 hi, lo; split_bf16(hwa[idx], hi, lo);
    g_ahi[idx] = hi; g_alo[idx] = lo;
}

__global__ void prep_wx(const float* __restrict__ Wx) {
    int idx = blockIdx.x * 256 + threadIdx.x;      // H_*IN_, [n][k]
    int n = idx / IN_, k = idx % IN_;
    __nv_bfloat16 hi, lo; split_bf16(Wx[(size_t)k * H_ + n], hi, lo);
    g_wxhi[idx] = hi; g_wxlo[idx] = lo;
}

__global__ void prep_wo(const float* __restrict__ Wout) {
    int idx = blockIdx.x * 256 + threadIdx.x;      // OUT_*H_, [o][k]
    if (idx >= OUT_ * H_) return;
    int o = idx >> 10, k = idx & 1023;
    __nv_bfloat16 hi, lo; split_bf16(Wout[(size_t)k * OUT_ + o], hi, lo);
    g_wohi[idx] = hi; g_wolo[idx] = lo;
}

// ---------------- generic 128x128 3-term mainloop body (used by rnn/xr) ----------------
// A tiles at buf+0 (hi) / +16384 (lo); B at +32768 (hi) / +49152 (lo)
__device__ __forceinline__ void mma128_chunk(uint32_t buf, int wm, int wn, int lane,
                                             float acc[2][8][4]) {
    const uint32_t pAhi = buf, pAlo = buf + 16384, pBhi = buf + 32768, pBlo = buf + 49152;
#pragma unroll
    for (int ks = 0; ks < 4; ks++) {
        uint32_t a[2][2][4];
        const int arow0 = wm + (lane & 7) + ((lane >> 3) & 1) * 8;
        const int acu   = 2 * ks + (lane >> 4);
#pragma unroll
        for (int mt = 0; mt < 2; mt++) {
            int r = arow0 + mt * 16;
            uint32_t off = (uint32_t)(r * 128 + ((acu ^ (r & 7)) << 4));
            LDSM4(a[0][mt][0], a[0][mt][1], a[0][mt][2], a[0][mt][3], pAhi + off);
            LDSM4(a[1][mt][0], a[1][mt][1], a[1][mt][2], a[1][mt][3], pAlo + off);
        }
        uint32_t b[2][8][2];
        const int brow0 = wn + (lane & 7) + ((lane >> 4) & 1) * 8;
        const int bcu   = 2 * ks + ((lane >> 3) & 1);
#pragma unroll
        for (int p = 0; p < 4; p++) {
            int r = brow0 + p * 16;
            uint32_t off = (uint32_t)(r * 128 + ((bcu ^ (r & 7)) << 4));
            uint32_t r0, r1, r2, r3;
            LDSM4(r0, r1, r2, r3, pBhi + off);
            b[0][2*p][0] = r0; b[0][2*p][1] = r1; b[0][2*p+1][0] = r2; b[0][2*p+1][1] = r3;
            LDSM4(r0, r1, r2, r3, pBlo + off);
            b[1][2*p][0] = r0; b[1][2*p][1] = r1; b[1][2*p+1][0] = r2; b[1][2*p+1][1] = r3;
        }
#pragma unroll
        for (int mt = 0; mt < 2; mt++)
#pragma unroll
            for (int nt = 0; nt < 8; nt++) MMA_BF16(acc[mt][nt], a[0][mt], b[0][nt]);
#pragma unroll
        for (int mt = 0; mt < 2; mt++)
#pragma unroll
            for (int nt = 0; nt < 8; nt++) MMA_BF16(acc[mt][nt], a[1][mt], b[0][nt]);
#pragma unroll
        for (int mt = 0; mt < 2; mt++)
#pragma unroll
            for (int nt = 0; nt < 8; nt++) MMA_BF16(acc[mt][nt], a[0][mt], b[1][nt]);
    }
}

// ---------------- xr GEMM (HMMA): g_xr = hwa @ Wx + bx ----------------
// grid (8 n-tiles, 16 m-tiles), 256 thr, dyn smem = 2*65536, K=2048 (32 chunks)
__global__ void __launch_bounds__(256) xr_mma(const float* __restrict__ bx) {
    extern __shared__ char smem[];
    uint32_t sb = smem_u32(smem);
    const int tid = threadIdx.x, wid = tid >> 5, lane = tid & 31;
    const int n0 = blockIdx.x * 128, m0 = blockIdx.y * 128;
    const int wm = (wid & 3) * 32, wn = (wid >> 2) * 64;

    const __nv_bfloat16* Ahi = g_ahi + (size_t)m0 * IN_;
    const __nv_bfloat16* Alo = g_alo + (size_t)m0 * IN_;
    const __nv_bfloat16* Bhi = g_wxhi + (size_t)n0 * IN_;
    const __nv_bfloat16* Blo = g_wxlo + (size_t)n0 * IN_;

    float acc[2][8][4] = {};
    issue_tile<128, IN_>(sb,         Ahi, tid);
    issue_tile<128, IN_>(sb + 16384, Alo, tid);
    issue_tile<128, IN_>(sb + 32768, Bhi, tid);
    issue_tile<128, IN_>(sb + 49152, Blo, tid);
    CP_COMMIT();

    for (int c = 0; c < 32; c++) {
        if (c < 31) {
            uint32_t nb = sb + ((c + 1) & 1) * 65536;
            int off = (c + 1) * 64;
            issue_tile<128, IN_>(nb,         Ahi + off, tid);
            issue_tile<128, IN_>(nb + 16384, Alo + off, tid);
            issue_tile<128, IN_>(nb + 32768, Bhi + off, tid);
            issue_tile<128, IN_>(nb + 49152, Blo + off, tid);
            CP_COMMIT();
            CP_WAIT1();
        } else {
            CP_WAIT0();
        }
        __syncthreads();
        mma128_chunk(sb + (c & 1) * 65536, wm, wn, lane, acc);
        __syncthreads();
    }

    const int g = lane >> 2, t4 = (lane & 3) * 2;
#pragma unroll
    for (int mt = 0; mt < 2; mt++)
#pragma unroll
        for (int nt = 0; nt < 8; nt++)
#pragma unroll
            for (int hf = 0; hf < 2; hf++) {
                int r = m0 + wm + mt * 16 + g + hf * 8;
                int c = n0 + wn + nt * 8 + t4;
                float2 bb = *(const float2*)&bx[c];
                float2 v;
                v.x = acc[mt][nt][hf * 2 + 0] + bb.x;
                v.y = acc[mt][nt][hf * 2 + 1] + bb.y;
                *(float2*)&g_xr[(size_t)r * H_ + c] = v;
            }
}

// ---------------- step 0: hs[0] = 0.5*tanh(x_r + bh), split bf16 ----------------
__global__ void step0_kernel(const float* __restrict__ bh) {
    int i = blockIdx.x * 256 + threadIdx.x;
    int c = i & (H_ - 1);
    float v = 0.5f * tanhf(g_xr[i] + bh[c]);
    __nv_bfloat16 hi, lo; split_bf16(v, hi, lo);
    g_hshi[i] = hi; g_hslo[i] = lo;
}

// ---------------- RNN step (HMMA) ----------------
// grid (8 n-tiles, 16 m-tiles), 256 thr, dyn smem = 2*65536
__global__ void __launch_bounds__(256) rnn_mma(const float* __restrict__ bh, int l) {
    extern __shared__ char smem[];
    uint32_t sb = smem_u32(smem);
    const int tid = threadIdx.x, wid = tid >> 5, lane = tid & 31;
    const int n0 = blockIdx.x * 128, m0 = blockIdx.y * 128;
    const int wm = (wid & 3) * 32, wn = (wid >> 2) * 64;

    const __nv_bfloat16* Ahi = g_hshi + ((size_t)(l - 1) * NB + m0) * H_;
    const __nv_bfloat16* Alo = g_hslo + ((size_t)(l - 1) * NB + m0) * H_;
    const __nv_bfloat16* Bhi = g_whhi + (size_t)n0 * H_;
    const __nv_bfloat16* Blo = g_whlo + (size_t)n0 * H_;

    float acc[2][8][4] = {};
    issue_tile<128, H_>(sb,         Ahi, tid);
    issue_tile<128, H_>(sb + 16384, Alo, tid);
    issue_tile<128, H_>(sb + 32768, Bhi, tid);
    issue_tile<128, H_>(sb + 49152, Blo, tid);
    CP_COMMIT();

    for (int c = 0; c < 16; c++) {
        if (c < 15) {
            uint32_t nb = sb + ((c + 1) & 1) * 65536;
            int off = (c + 1) * 64;
            issue_tile<128, H_>(nb,         Ahi + off, tid);
            issue_tile<128, H_>(nb + 16384, Alo + off, tid);
            issue_tile<128, H_>(nb + 32768, Bhi + off, tid);
            issue_tile<128, H_>(nb + 49152, Blo + off, tid);
            CP_COMMIT();
            CP_WAIT1();
        } else {
            CP_WAIT0();
        }
        __syncthreads();
        mma128_chunk(sb + (c & 1) * 65536, wm, wn, lane, acc);
        __syncthreads();
    }

    const int g = lane >> 2, t4 = (lane & 3) * 2;
    const size_t prevB = (size_t)(l - 1) * NB * H_;
    const size_t curB  = (size_t)l * NB * H_;
#pragma unroll
    for (int mt = 0; mt < 2; mt++)
#pragma unroll
        for (int nt = 0; nt < 8; nt++)
#pragma unroll
            for (int hf = 0; hf < 2; hf++) {
                int r = m0 + wm + mt * 16 + g + hf * 8;
                int c = n0 + wn + nt * 8 + t4;
                size_t base = (size_t)r * H_ + c;
                float ax = acc[mt][nt][hf * 2 + 0];
                float ay = acc[mt][nt][hf * 2 + 1];
                float2 xr2 = *(const float2*)&g_xr[base];
                float2 bh2 = *(const float2*)&bh[c];
                __nv_bfloat162 ph = *(const __nv_bfloat162*)&g_hshi[prevB + base];
                __nv_bfloat162 pl = *(const __nv_bfloat162*)&g_hslo[prevB + base];
                float hp0 = __bfloat162float(ph.x) + __bfloat162float(pl.x);
                float hp1 = __bfloat162float(ph.y) + __bfloat162float(pl.y);
                float h0 = 0.5f * hp0 + 0.5f * tanhf(xr2.x + ax + bh2.x);
                float h1 = 0.5f * hp1 + 0.5f * tanhf(xr2.y + ay + bh2.y);
                __nv_bfloat162 vh, vl;
                __nv_bfloat16 hh, hl;
                split_bf16(h0, hh, hl); vh.x = hh; vl.x = hl;
                split_bf16(h1, hh, hl); vh.y = hh; vl.y = hl;
                *(__nv_bfloat162*)&g_hshi[curB + base] = vh;
                *(__nv_bfloat162*)&g_hslo[curB + base] = vl;
            }
}

// ---------------- conv (HMMA): tap-decomposed GEMM, CTA tile 128(n) x 256(branch) ----------------
// grid (16 m-tiles, 4 branches, 32 l), 256 thr, warp tile 64x64, dyn smem = 2*98304
__global__ void __launch_bounds__(256, 1) conv_mma() {
    extern __shared__ char smem[];
    uint32_t sb = smem_u32(smem);
    const int tid = threadIdx.x, wid = tid >> 5, lane = tid & 31;
    const int m0 = blockIdx.x * 128;
    const int br = blockIdx.y;
    const int l  = blockIdx.z;
    const int kb = 2 * br + 1;
    const int sbase = (br == 0) ? 0 : (br == 1) ? 1 : (br == 2) ? 4 : 9;
    const int wm = (wid & 1) * 64, wn = (wid >> 1) * 64;

    int lsrcs[7], slabs[7], ntap = 0;
    for (int t = 0; t < kb; t++) {
        int lsrc = l + t - br;
        if (lsrc >= 0 && lsrc < L_) { lsrcs[ntap] = lsrc; slabs[ntap] = sbase + t; ntap++; }
    }
    const int C = ntap * 16;

    float acc[4][8][4] = {};
    {
        const __nv_bfloat16* Ahi = g_hshi + ((size_t)lsrcs[0] * NB + m0) * H_;
        const __nv_bfloat16* Alo = g_hslo + ((size_t)lsrcs[0] * NB + m0) * H_;
        const __nv_bfloat16* Bhi = g_wchi + (size_t)slabs[0] * QH * H_;
        const __nv_bfloat16* Blo = g_wclo + (size_t)slabs[0] * QH * H_;
        issue_tile<128, H_>(sb,         Ahi, tid);
        issue_tile<128, H_>(sb + 16384, Alo, tid);
        issue_tile<256, H_>(sb + 32768, Bhi, tid);
        issue_tile<256, H_>(sb + 65536, Blo, tid);
        CP_COMMIT();
    }
    for (int c = 0; c < C; c++) {
        if (c + 1 < C) {
            int tap = (c + 1) >> 4, kc = (c + 1) & 15;
            const __nv_bfloat16* Ahi = g_hshi + ((size_t)lsrcs[tap] * NB + m0) * H_ + kc * 64;
            const __nv_bfloat16* Alo = g_hslo + ((size_t)lsrcs[tap] * NB + m0) * H_ + kc * 64;
            const __nv_bfloat16* Bhi = g_wchi + (size_t)slabs[tap] * QH * H_ + kc * 64;
            const __nv_bfloat16* Blo = g_wclo + (size_t)slabs[tap] * QH * H_ + kc * 64;
            uint32_t nb = sb + ((c + 1) & 1) * 98304;
            issue_tile<128, H_>(nb,         Ahi, tid);
            issue_tile<128, H_>(nb + 16384, Alo, tid);
            issue_tile<256, H_>(nb + 32768, Bhi, tid);
            issue_tile<256, H_>(nb + 65536, Blo, tid);
            CP_COMMIT();
            CP_WAIT1();
        } else {
            CP_WAIT0();
        }
        __syncthreads();
        {
            uint32_t buf = sb + (c & 1) * 98304;
            const uint32_t pAhi = buf, pAlo = buf + 16384, pBhi = buf + 32768, pBlo = buf + 65536;
#pragma unroll
            for (int ks = 0; ks < 4; ks++) {
                uint32_t ah[4][4], al[4][4];
                const int arow0 = wm + (lane & 7) + ((lane >> 3) & 1) * 8;
                const int acu   = 2 * ks + (lane >> 4);
#pragma unroll
                for (int mt = 0; mt < 4; mt++) {
                    int r = arow0 + mt * 16;
                    uint32_t off = (uint32_t)(r * 128 + ((acu ^ (r & 7)) << 4));
                    LDSM4(ah[mt][0], ah[mt][1], ah[mt][2], ah[mt][3], pAhi + off);
                    LDSM4(al[mt][0], al[mt][1], al[mt][2], al[mt][3], pAlo + off);
                }
                uint32_t b[8][2];
                const int brow0 = wn + (lane & 7) + ((lane >> 4) & 1) * 8;
                const int bcu   = 2 * ks + ((lane >> 3) & 1);
#pragma unroll
                for (int p = 0; p < 4; p++) {
                    int r = brow0 + p * 16;
                    uint32_t off = (uint32_t)(r * 128 + ((bcu ^ (r & 7)) << 4));
                    uint32_t r0, r1, r2, r3;
                    LDSM4(r0, r1, r2, r3, pBhi + off);
                    b[2*p][0] = r0; b[2*p][1] = r1; b[2*p+1][0] = r2; b[2*p+1][1] = r3;
                }
#pragma unroll
                for (int mt = 0; mt < 4; mt++)
#pragma unroll
                    for (int nt = 0; nt < 8; nt++) MMA_BF16(acc[mt][nt], ah[mt], b[nt]);
#pragma unroll
                for (int mt = 0; mt < 4; mt++)
#pragma unroll
                    for (int nt = 0; nt < 8; nt++) MMA_BF16(acc[mt][nt], al[mt], b[nt]);
#pragma unroll
                for (int p = 0; p < 4; p++) {
                    int r = brow0 + p * 16;
                    uint32_t off = (uint32_t)(r * 128 + ((bcu ^ (r & 7)) << 4));
                    uint32_t r0, r1, r2, r3;
                    LDSM4(r0, r1, r2, r3, pBlo + off);
                    b[2*p][0] = r0; b[2*p][1] = r1; b[2*p+1][0] = r2; b[2*p+1][1] = r3;
                }
#pragma unroll
                for (int mt = 0; mt < 4; mt++)
#pragma unroll
                    for (int nt = 0; nt < 8; nt++) MMA_BF16(acc[mt][nt], ah[mt], b[nt]);
            }
        }
        __syncthreads();
    }

    // epilogue: bias add, split-write y (hi/lo bf16)
    const int g = lane >> 2, t4 = (lane & 3) * 2;
#pragma unroll
    for (int mt = 0; mt < 4; mt++)
#pragma unroll
        for (int nt = 0; nt < 8; nt++)
#pragma unroll
            for (int hf = 0; hf < 2; hf++) {
                int r = m0 + wm + mt * 16 + g + hf * 8;
                int c = br * 256 + wn + nt * 8 + t4;
                float2 bb = *(const float2*)&g_bias[c];
                float s0 = acc[mt][nt][hf * 2 + 0] + bb.x;
                float s1 = acc[mt][nt][hf * 2 + 1] + bb.y;
                __nv_bfloat162 vh, vl;
                __nv_bfloat16 hh, hl;
                split_bf16(s0, hh, hl); vh.x = hh; vl.x = hl;
                split_bf16(s1, hh, hl); vh.y = hh; vl.y = hl;
                size_t base = ((size_t)l * NB + r) * H_ + c;
                *(__nv_bfloat162*)&g_yhi[base] = vh;
                *(__nv_bfloat162*)&g_ylo[base] = vl;
            }
}

// ---------------- BN stats (reads split y) ----------------
__global__ void stats_partial() {
    __shared__ float ss[8][32], sq[8][32];
    int tx = threadIdx.x, ty = threadIdx.y;
    int c  = blockIdx.x * 32 + tx;
    int r0 = blockIdx.y * 1024;
    float s = 0.f, q = 0.f;
    for (int r = r0 + ty; r < r0 + 1024; r += 8) {
        size_t i = (size_t)r * H_ + c;
        float v = __bfloat162float(g_yhi[i]) + __bfloat162float(g_ylo[i]);
        s += v; q += v * v;
    }
    ss[ty][tx] = s; sq[ty][tx] = q;
    __syncthreads();
    if (ty == 0) {
        float S = 0.f, Q = 0.f;
#pragma unroll
        for (int j = 0; j < 8; j++) { S += ss[j][tx]; Q += sq[j][tx]; }
        g_psum  [blockIdx.y * H_ + c] = S;
        g_psumsq[blockIdx.y * H_ + c] = Q;
    }
}

__global__ void finalize_kernel(const float* __restrict__ gamma, const float* __restrict__ beta) {
    int c = blockIdx.x * 256 + threadIdx.x;
    if (c >= H_) return;
    float s = 0.f, q = 0.f;
    for (int p = 0; p < 64; p++) { s += g_psum[p * H_ + c]; q += g_psumsq[p * H_ + c]; }
    const float invM = 1.0f / (float)(NB * L_);
    float mean = s * invM;
    float var  = q * invM - mean * mean;
    float rstd = rsqrtf(var + 1e-5f);
    float sc   = rstd * gamma[c];
    g_scale[c] = sc;
    g_shift[c] = beta[c] - mean * sc;
}

// ---------------- in-place BN+PReLU + re-split of y ----------------
__global__ void presplit_y(const float* __restrict__ prelu) {
    size_t i = (size_t)blockIdx.x * 256 + threadIdx.x;
    int c = (int)(i & (H_ - 1));
    float pa = *prelu;
    float v = __bfloat162float(g_yhi[i]) + __bfloat162float(g_ylo[i]);
    float w = v * g_scale[c] + g_shift[c];
    w = (w > 0.f) ? w : pa * w;
    __nv_bfloat16 hi, lo; split_bf16(w, hi, lo);
    g_yhi[i] = hi; g_ylo[i] = lo;
}

// ---------------- out GEMM (HMMA): out = A @ WoutT + bout, A rows = l*NB+n ----------------
// grid 256 CTAs (M=65536/256), 256 thr, warp tile 32x64, dyn smem = 2*81920
__global__ void __launch_bounds__(256, 1) out_mma(const float* __restrict__ bout,
                                                  float* __restrict__ out) {
    extern __shared__ char smem[];
    uint32_t sb = smem_u32(smem);
    const int tid = threadIdx.x, wid = tid >> 5, lane = tid & 31;
    const int m0 = blockIdx.x * 256;
    const int wm = wid * 32;

    const __nv_bfloat16* Ahi = g_yhi + (size_t)m0 * H_;
    const __nv_bfloat16* Alo = g_ylo + (size_t)m0 * H_;

    float acc[2][8][4] = {};
    // chunk layout: Ahi 32K | Alo 32K | Bhi 8K | Blo 8K = 80K, x2
    issue_tile<256, H_>(sb,         Ahi, tid);
    issue_tile<256, H_>(sb + 32768, Alo, tid);
    issue_tile<64,  H_>(sb + 65536, g_wohi, tid);
    issue_tile<64,  H_>(sb + 73728, g_wolo, tid);
    CP_COMMIT();

    for (int c = 0; c < 16; c++) {
        if (c < 15) {
            uint32_t nb = sb + ((c + 1) & 1) * 81920;
            int off = (c + 1) * 64;
            issue_tile<256, H_>(nb,         Ahi + off, tid);
            issue_tile<256, H_>(nb + 32768, Alo + off, tid);
            issue_tile<64,  H_>(nb + 65536, g_wohi + off, tid);
            issue_tile<64,  H_>(nb + 73728, g_wolo + off, tid);
            CP_COMMIT();
            CP_WAIT1();
        } else {
            CP_WAIT0();
        }
        __syncthreads();
        {
            uint32_t buf = sb + (c & 1) * 81920;
            const uint32_t pAhi = buf, pAlo = buf + 32768, pBhi = buf + 65536, pBlo = buf + 73728;
#pragma unroll
            for (int ks = 0; ks < 4; ks++) {
                uint32_t a[2][2][4];
                const int arow0 = wm + (lane & 7) + ((lane >> 3) & 1) * 8;
                const int acu   = 2 * ks + (lane >> 4);
#pragma unroll
                for (int mt = 0; mt < 2; mt++) {
                    int r = arow0 + mt * 16;
                    uint32_t off = (uint32_t)(r * 128 + ((acu ^ (r & 7)) << 4));
                    LDSM4(a[0][mt][0], a[0][mt][1], a[0][mt][2], a[0][mt][3], pAhi + off);
                    LDSM4(a[1][mt][0], a[1][mt][1], a[1][mt][2], a[1][mt][3], pAlo + off);
                }
                uint32_t b[2][8][2];
                const int brow0 = (lane & 7) + ((lane >> 4) & 1) * 8;
                const int bcu   = 2 * ks + ((lane >> 3) & 1);
#pragma unroll
                for (int p = 0; p < 4; p++) {
                    int r = brow0 + p * 16;
                    uint32_t off = (uint32_t)(r * 128 + ((bcu ^ (r & 7)) << 4));
                    uint32_t r0, r1, r2, r3;
                    LDSM4(r0, r1, r2, r3, pBhi + off);
                    b[0][2*p][0] = r0; b[0][2*p][1] = r1; b[0][2*p+1][0] = r2; b[0][2*p+1][1] = r3;
                    LDSM4(r0, r1, r2, r3, pBlo + off);
                    b[1][2*p][0] = r0; b[1][2*p][1] = r1; b[1][2*p+1][0] = r2; b[1][2*p+1][1] = r3;
                }
#pragma unroll
                for (int mt = 0; mt < 2; mt++)
#pragma unroll
                    for (int nt = 0; nt < 8; nt++) MMA_BF16(acc[mt][nt], a[0][mt], b[0][nt]);
#pragma unroll
                for (int mt = 0; mt < 2; mt++)
#pragma unroll
                    for (int nt = 0; nt < 8; nt++) MMA_BF16(acc[mt][nt], a[1][mt], b[0][nt]);
#pragma unroll
                for (int mt = 0; mt < 2; mt++)
#pragma unroll
                    for (int nt = 0; nt < 8; nt++) MMA_BF16(acc[mt][nt], a[0][mt], b[1][nt]);
            }
        }
        __syncthreads();
    }

    const int g = lane >> 2, t4 = (lane & 3) * 2;
#pragma unroll
    for (int mt = 0; mt < 2; mt++)
#pragma unroll
        for (int nt = 0; nt < 8; nt++)
#pragma unroll
            for (int hf = 0; hf < 2; hf++) {
                int r = m0 + wm + mt * 16 + g + hf * 8;     // r = l*NB + nn
                int c = nt * 8 + t4;
                int l  = r >> 11;                            // / NB
                int nn = r & (NB - 1);
                float2 bb = *(const float2*)&bout[c];
                float2 v;
                v.x = acc[mt][nt][hf * 2 + 0] + bb.x;
                v.y = acc[mt][nt][hf * 2 + 1] + bb.y;
                *(float2*)&out[((size_t)nn * L_ + l) * OUT_ + c] = v;
            }
}

// ---------------- launch ----------------
#define RNN_SMEM  (2 * 65536)
#define CONV_SMEM (2 * 98304)
#define OUT_SMEM  (2 * 81920)

extern "C" void kernel_launch(void* const* d_in, const int* in_sizes, int n_in,
                              void* d_out, int out_size)
{
    const float* hwa   = (const float*)d_in[0];
    const float* Wx    = (const float*)d_in[1];
    const float* bx    = (const float*)d_in[2];
    const float* Wh    = (const float*)d_in[3];
    const float* bh    = (const float*)d_in[4];
    const float* w1    = (const float*)d_in[5];
    const float* b1    = (const float*)d_in[6];
    const float* w3    = (const float*)d_in[7];
    const float* b3    = (const float*)d_in[8];
    const float* w5    = (const float*)d_in[9];
    const float* b5    = (const float*)d_in[10];
    const float* w7    = (const float*)d_in[11];
    const float* b7    = (const float*)d_in[12];
    const float* gamma = (const float*)d_in[13];
    const float* beta  = (const float*)d_in[14];
    const float* prelu = (const float*)d_in[15];
    const float* Wout  = (const float*)d_in[16];
    const float* bout  = (const float*)d_in[17];
    float* out = (float*)d_out;

    cudaFuncSetAttribute(xr_mma,   cudaFuncAttributeMaxDynamicSharedMemorySize, RNN_SMEM);
    cudaFuncSetAttribute(rnn_mma,  cudaFuncAttributeMaxDynamicSharedMemorySize, RNN_SMEM);
    cudaFuncSetAttribute(conv_mma, cudaFuncAttributeMaxDynamicSharedMemorySize, CONV_SMEM);
    cudaFuncSetAttribute(out_mma,  cudaFuncAttributeMaxDynamicSharedMemorySize, OUT_SMEM);

    prep_wh<<<(H_ * H_) / 256, 256>>>(Wh);
    prep_wc<<<(16 * QH * H_) / 256, 256>>>(w1, b1, w3, b3, w5, b5, w7, b7);
    prep_hwa<<<(NB * IN_) / 256, 256>>>(hwa);
    prep_wx<<<(H_ * IN_) / 256, 256>>>(Wx);
    prep_wo<<<(OUT_ * H_ + 255) / 256, 256>>>(Wout);

    xr_mma<<<dim3(H_ / 128, NB / 128), 256, RNN_SMEM>>>(bx);
    step0_kernel<<<(NB * H_) / 256, 256>>>(bh);
    for (int l = 1; l < L_; l++)
        rnn_mma<<<dim3(H_ / 128, NB / 128), 256, RNN_SMEM>>>(bh, l);
    conv_mma<<<dim3(NB / 128, 4, L_), 256, CONV_SMEM>>>();
    stats_partial<<<dim3(H_ / 32, 64), dim3(32, 8)>>>();
    finalize_kernel<<<(H_ + 255) / 256, 256>>>(gamma, beta);
    presplit_y<<<((size_t)L_ * NB * H_) / 256, 256>>>(prelu);
    out_mma<<<(L_ * NB) / 256, 256, OUT_SMEM>>>(bout, out);
}